// round 2
// baseline (speedup 1.0000x reference)
#include <cuda_runtime.h>

#define NN 4096
#define DD 512
#define EE 65536
#define NHOPS 10

// ---------------- static device scratch (allocation-free rule) ----------------
__device__ float g_X0[(size_t)NN * NN];   // x0 term for current APPNP phase
__device__ float g_Ha[(size_t)NN * NN];   // ping
__device__ float g_Hb[(size_t)NN * NN];   // pong
__device__ int   g_rowptr[NN + 1];
__device__ int   g_cur[NN];
__device__ int   g_cols[EE + NN];
__device__ float g_vals[EE + NN];
__device__ float g_dis[NN];
__device__ float g_sq[NN];
__device__ int   g_degdst[NN];
__device__ int   g_degrow[NN];

// ---------------- graph preprocessing ----------------
__global__ void init_kernel() {
    int i = blockIdx.x * blockDim.x + threadIdx.x;
    if (i < NN) { g_degdst[i] = 1; g_degrow[i] = 0; }
}

__global__ void count_kernel(const int* __restrict__ src, const int* __restrict__ dst) {
    int i = blockIdx.x * blockDim.x + threadIdx.x;
    if (i < EE) {
        atomicAdd(&g_degdst[dst[i]], 1);
        atomicAdd(&g_degrow[src[i]], 1);
    }
}

// single block, 1024 threads, 4 elements each: exclusive scan of g_degdst -> rowptr
__global__ void scan_kernel() {
    __shared__ int part[1024];
    int t = threadIdx.x;
    int v[4];
    int s = 0;
#pragma unroll
    for (int j = 0; j < 4; j++) { v[j] = g_degdst[t * 4 + j]; s += v[j]; }
    part[t] = s;
    __syncthreads();
    for (int off = 1; off < 1024; off <<= 1) {
        int x = 0;
        if (t >= off) x = part[t - off];
        __syncthreads();
        if (t >= off) part[t] += x;
        __syncthreads();
    }
    int base = part[t] - s; // exclusive
    int run = base;
#pragma unroll
    for (int j = 0; j < 4; j++) {
        int idx = t * 4 + j;
        g_rowptr[idx] = run;
        g_cur[idx] = run;
        g_dis[idx] = rsqrtf((float)v[j]);
        run += v[j];
    }
    if (t == 1023) g_rowptr[NN] = part[1023];
}

__global__ void fill_kernel(const int* __restrict__ src, const int* __restrict__ dst) {
    int i = blockIdx.x * blockDim.x + threadIdx.x;
    if (i < EE) {
        int s = src[i], d = dst[i];
        int p = atomicAdd(&g_cur[d], 1);
        g_cols[p] = s;
        g_vals[p] = g_dis[s] * g_dis[d];
    } else if (i < EE + NN) {
        int n = i - EE;
        int p = atomicAdd(&g_cur[n], 1);
        g_cols[p] = n;
        g_vals[p] = g_dis[n] * g_dis[n];
    }
}

// ---------------- sq[i] = sum_d w_d * x[i,d]^2 ----------------
__global__ void sq_kernel(const float* __restrict__ x, const float* __restrict__ w) {
    __shared__ float red[4];
    int r = blockIdx.x;
    int t = threadIdx.x; // 128
    float s = 0.f;
    for (int d = t; d < DD; d += 128) {
        float xv = x[r * DD + d];
        s += w[d] * xv * xv;
    }
#pragma unroll
    for (int o = 16; o > 0; o >>= 1) s += __shfl_xor_sync(0xffffffffu, s, o);
    if ((t & 31) == 0) red[t >> 5] = s;
    __syncthreads();
    if (t == 0) g_sq[r] = red[0] + red[1] + red[2] + red[3];
}

// ---------------- K = sq_i + sq_j - 2*(x.w) x^T, diag = 1 ----------------
// writes K into g_X0 and g_Ha
__global__ __launch_bounds__(256, 2) void gemm_kernel(const float* __restrict__ x,
                                                      const float* __restrict__ w) {
    __shared__ float As[16][132];
    __shared__ float Bs[16][132];
    int tid = threadIdx.x;
    int rowA0 = blockIdx.y << 7;
    int colB0 = blockIdx.x << 7;
    int rb = (tid >> 4) << 3;
    int cb = (tid & 15) << 3;

    float acc[8][8];
#pragma unroll
    for (int i = 0; i < 8; i++)
#pragma unroll
        for (int j = 0; j < 8; j++) acc[i][j] = 0.f;

    for (int kt = 0; kt < DD; kt += 16) {
        __syncthreads();
#pragma unroll
        for (int l = 0; l < 2; l++) {
            int f = tid + (l << 8);
            int i = f >> 2;
            int kq = f & 3;
            float4 wa = *(const float4*)(w + kt + (kq << 2));
            float4 va = *(const float4*)(x + (size_t)(rowA0 + i) * DD + kt + (kq << 2));
            float4 vb = *(const float4*)(x + (size_t)(colB0 + i) * DD + kt + (kq << 2));
            As[(kq << 2) + 0][i] = va.x * wa.x;
            As[(kq << 2) + 1][i] = va.y * wa.y;
            As[(kq << 2) + 2][i] = va.z * wa.z;
            As[(kq << 2) + 3][i] = va.w * wa.w;
            Bs[(kq << 2) + 0][i] = vb.x;
            Bs[(kq << 2) + 1][i] = vb.y;
            Bs[(kq << 2) + 2][i] = vb.z;
            Bs[(kq << 2) + 3][i] = vb.w;
        }
        __syncthreads();
#pragma unroll
        for (int k = 0; k < 16; k++) {
            float a[8], b[8];
            *(float4*)(a) = *(const float4*)&As[k][rb];
            *(float4*)(a + 4) = *(const float4*)&As[k][rb + 4];
            *(float4*)(b) = *(const float4*)&Bs[k][cb];
            *(float4*)(b + 4) = *(const float4*)&Bs[k][cb + 4];
#pragma unroll
            for (int i = 0; i < 8; i++)
#pragma unroll
                for (int j = 0; j < 8; j++) acc[i][j] = fmaf(a[i], b[j], acc[i][j]);
        }
    }

    // epilogue: K = sq_i + sq_j - 2*acc ; diag = 1
#pragma unroll
    for (int ii = 0; ii < 8; ii++) {
        int gi = rowA0 + rb + ii;
        float sqi = __ldg(&g_sq[gi]);
        float tmp[8];
#pragma unroll
        for (int jj = 0; jj < 8; jj++) {
            int gj = colB0 + cb + jj;
            float v = sqi + __ldg(&g_sq[gj]) - 2.f * acc[ii][jj];
            if (gi == gj) v = 1.f;
            tmp[jj] = v;
        }
        int off = gi * NN + colB0 + cb;
        *(float4*)(g_X0 + off) = *(float4*)tmp;
        *(float4*)(g_X0 + off + 4) = *(float4*)(tmp + 4);
        *(float4*)(g_Ha + off) = *(float4*)tmp;
        *(float4*)(g_Ha + off + 4) = *(float4*)(tmp + 4);
    }
}

// ---------------- one APPNP hop: O = 0.5 * A_hat * H + 0.5 * X0 ----------------
// dir == 0: H = g_Ha, O = g_Hb ; dir == 1: H = g_Hb, O = g_Ha
__global__ __launch_bounds__(256) void spmm_kernel(int dir) {
    __shared__ int s_col[256];
    __shared__ float s_val[256];
    const float* __restrict__ H = dir ? g_Hb : g_Ha;
    float* __restrict__ O = dir ? g_Ha : g_Hb;
    int r = blockIdx.x;
    int c = (blockIdx.y << 10) + (threadIdx.x << 2);
    int beg = g_rowptr[r];
    int end = g_rowptr[r + 1];

    float4 acc = make_float4(0.f, 0.f, 0.f, 0.f);
    for (int base = beg; base < end; base += 256) {
        int cnt = min(256, end - base);
        __syncthreads();
        if (threadIdx.x < cnt) {
            s_col[threadIdx.x] = g_cols[base + threadIdx.x];
            s_val[threadIdx.x] = g_vals[base + threadIdx.x];
        }
        __syncthreads();
        int e = 0;
        for (; e + 4 <= cnt; e += 4) {
            int i0 = s_col[e + 0], i1 = s_col[e + 1], i2 = s_col[e + 2], i3 = s_col[e + 3];
            float v0 = s_val[e + 0], v1 = s_val[e + 1], v2 = s_val[e + 2], v3 = s_val[e + 3];
            float4 h0 = *(const float4*)(H + (i0 << 12) + c);
            float4 h1 = *(const float4*)(H + (i1 << 12) + c);
            float4 h2 = *(const float4*)(H + (i2 << 12) + c);
            float4 h3 = *(const float4*)(H + (i3 << 12) + c);
            acc.x = fmaf(v0, h0.x, acc.x); acc.y = fmaf(v0, h0.y, acc.y);
            acc.z = fmaf(v0, h0.z, acc.z); acc.w = fmaf(v0, h0.w, acc.w);
            acc.x = fmaf(v1, h1.x, acc.x); acc.y = fmaf(v1, h1.y, acc.y);
            acc.z = fmaf(v1, h1.z, acc.z); acc.w = fmaf(v1, h1.w, acc.w);
            acc.x = fmaf(v2, h2.x, acc.x); acc.y = fmaf(v2, h2.y, acc.y);
            acc.z = fmaf(v2, h2.z, acc.z); acc.w = fmaf(v2, h2.w, acc.w);
            acc.x = fmaf(v3, h3.x, acc.x); acc.y = fmaf(v3, h3.y, acc.y);
            acc.z = fmaf(v3, h3.z, acc.z); acc.w = fmaf(v3, h3.w, acc.w);
        }
        for (; e < cnt; e++) {
            int i0 = s_col[e];
            float v0 = s_val[e];
            float4 h0 = *(const float4*)(H + (i0 << 12) + c);
            acc.x = fmaf(v0, h0.x, acc.x); acc.y = fmaf(v0, h0.y, acc.y);
            acc.z = fmaf(v0, h0.z, acc.z); acc.w = fmaf(v0, h0.w, acc.w);
        }
    }
    float4 x0 = *(const float4*)(g_X0 + (r << 12) + c);
    float4 o;
    o.x = 0.5f * acc.x + 0.5f * x0.x;
    o.y = 0.5f * acc.y + 0.5f * x0.y;
    o.z = 0.5f * acc.z + 0.5f * x0.z;
    o.w = 0.5f * acc.w + 0.5f * x0.w;
    *(float4*)(O + (r << 12) + c) = o;
}

// ---------------- transpose g_Ha -> (g_X0 and g_Hb) ----------------
__global__ void transpose_kernel() {
    __shared__ float t[32][33];
    int xi = blockIdx.x * 32 + threadIdx.x;
    int y0 = blockIdx.y * 32;
#pragma unroll
    for (int j = threadIdx.y; j < 32; j += 8)
        t[j][threadIdx.x] = g_Ha[(size_t)(y0 + j) * NN + xi];
    __syncthreads();
    int xo = y0 + threadIdx.x;
    int yo0 = blockIdx.x * 32;
#pragma unroll
    for (int j = threadIdx.y; j < 32; j += 8) {
        float v = t[threadIdx.x][j];
        g_X0[(size_t)(yo0 + j) * NN + xo] = v;
        g_Hb[(size_t)(yo0 + j) * NN + xo] = v;
    }
}

// ---------------- final: out[i,j] = Hb[j,i] ; diag scaled by 1/(deg_row+1) ----------------
__global__ void final_kernel(float* __restrict__ out) {
    __shared__ float t[32][33];
    int xi = blockIdx.x * 32 + threadIdx.x;
    int y0 = blockIdx.y * 32;
#pragma unroll
    for (int j = threadIdx.y; j < 32; j += 8)
        t[j][threadIdx.x] = g_Hb[(size_t)(y0 + j) * NN + xi];
    __syncthreads();
    int b = y0 + threadIdx.x;       // output col
    int a0 = blockIdx.x * 32;       // output row base
#pragma unroll
    for (int j = threadIdx.y; j < 32; j += 8) {
        int a = a0 + j;
        float v = t[threadIdx.x][j]; // = Hb[b][a]
        if (a == b) v *= 1.0f / ((float)g_degrow[a] + 1.0f);
        out[(size_t)a * NN + b] = v;
    }
}

extern "C" void kernel_launch(void* const* d_in, const int* in_sizes, int n_in,
                              void* d_out, int out_size) {
    const float* x = (const float*)d_in[0];
    const float* w = (const float*)d_in[1];
    const int* ei = (const int*)d_in[2];
    const int* src = ei;
    const int* dst = ei + EE;
    float* out = (float*)d_out;

    init_kernel<<<(NN + 255) / 256, 256>>>();
    count_kernel<<<(EE + 255) / 256, 256>>>(src, dst);
    scan_kernel<<<1, 1024>>>();
    fill_kernel<<<(EE + NN + 255) / 256, 256>>>(src, dst);

    sq_kernel<<<NN, 128>>>(x, w);
    dim3 gg(NN / 128, NN / 128);
    gemm_kernel<<<gg, 256>>>(x, w);

    dim3 gs(NN, 4);
    // phase 1: H starts in g_Ha, 10 hops -> result in g_Ha
    for (int h = 0; h < NHOPS; h++) spmm_kernel<<<gs, 256>>>(h & 1);

    // X0 = result^T, start buffer g_Hb = result^T
    transpose_kernel<<<dim3(NN / 32, NN / 32), dim3(32, 8)>>>();

    // phase 2: H starts in g_Hb, 10 hops -> result in g_Hb
    for (int h = 0; h < NHOPS; h++) spmm_kernel<<<gs, 256>>>((h & 1) ^ 1);

    final_kernel<<<dim3(NN / 32, NN / 32), dim3(32, 8)>>>(out);
    (void)in_sizes; (void)n_in; (void)out_size;
}

// round 3
// speedup vs baseline: 1.1476x; 1.1476x over previous
#include <cuda_runtime.h>

#define NN 4096
#define DD 512
#define EE 65536
#define NHOPS 10

// ---------------- static device scratch (allocation-free rule) ----------------
__device__ float g_X0[(size_t)NN * NN];   // x0 term for current APPNP phase
__device__ float g_Ha[(size_t)NN * NN];   // ping
__device__ float g_Hb[(size_t)NN * NN];   // pong
__device__ int   g_rowptr[NN + 1];
__device__ int   g_cur[NN];
__device__ int   g_cols[EE + NN];
__device__ float g_vals[EE + NN];
__device__ float g_dis[NN];
__device__ float g_sq[NN];
__device__ int   g_degdst[NN];
__device__ int   g_degrow[NN];

// ---------------- graph preprocessing ----------------
__global__ void init_kernel() {
    int i = blockIdx.x * blockDim.x + threadIdx.x;
    if (i < NN) { g_degdst[i] = 1; g_degrow[i] = 0; }
}

__global__ void count_kernel(const int* __restrict__ src, const int* __restrict__ dst) {
    int i = blockIdx.x * blockDim.x + threadIdx.x;
    if (i < EE) {
        atomicAdd(&g_degdst[dst[i]], 1);
        atomicAdd(&g_degrow[src[i]], 1);
    }
}

// single block, 1024 threads, 4 elements each: exclusive scan of g_degdst -> rowptr
__global__ void scan_kernel() {
    __shared__ int part[1024];
    int t = threadIdx.x;
    int v[4];
    int s = 0;
#pragma unroll
    for (int j = 0; j < 4; j++) { v[j] = g_degdst[t * 4 + j]; s += v[j]; }
    part[t] = s;
    __syncthreads();
    for (int off = 1; off < 1024; off <<= 1) {
        int x = 0;
        if (t >= off) x = part[t - off];
        __syncthreads();
        if (t >= off) part[t] += x;
        __syncthreads();
    }
    int base = part[t] - s; // exclusive
    int run = base;
#pragma unroll
    for (int j = 0; j < 4; j++) {
        int idx = t * 4 + j;
        g_rowptr[idx] = run;
        g_cur[idx] = run;
        g_dis[idx] = rsqrtf((float)v[j]);
        run += v[j];
    }
    if (t == 1023) g_rowptr[NN] = part[1023];
}

__global__ void fill_kernel(const int* __restrict__ src, const int* __restrict__ dst) {
    int i = blockIdx.x * blockDim.x + threadIdx.x;
    if (i < EE) {
        int s = src[i], d = dst[i];
        int p = atomicAdd(&g_cur[d], 1);
        g_cols[p] = s;
        g_vals[p] = g_dis[s] * g_dis[d];
    } else if (i < EE + NN) {
        int n = i - EE;
        int p = atomicAdd(&g_cur[n], 1);
        g_cols[p] = n;
        g_vals[p] = g_dis[n] * g_dis[n];
    }
}

// ---------------- sq[i] = sum_d w_d * x[i,d]^2 ----------------
__global__ void sq_kernel(const float* __restrict__ x, const float* __restrict__ w) {
    __shared__ float red[4];
    int r = blockIdx.x;
    int t = threadIdx.x; // 128
    float s = 0.f;
    for (int d = t; d < DD; d += 128) {
        float xv = x[r * DD + d];
        s += w[d] * xv * xv;
    }
#pragma unroll
    for (int o = 16; o > 0; o >>= 1) s += __shfl_xor_sync(0xffffffffu, s, o);
    if ((t & 31) == 0) red[t >> 5] = s;
    __syncthreads();
    if (t == 0) g_sq[r] = red[0] + red[1] + red[2] + red[3];
}

// ---------------- K = sq_i + sq_j - 2*(x.w) x^T, diag = 1 (SYMMETRIC) ----------------
// Only lower-triangular 128x128 tiles are computed (528 blocks); each tile is
// written to g_X0 and g_Ha at (bi,bj) and mirrored (transposed) at (bj,bi).
__global__ __launch_bounds__(256, 2) void gemm_kernel(const float* __restrict__ x,
                                                      const float* __restrict__ w) {
    __shared__ float As[16][132];
    __shared__ float Bs[16][132];
    int tid = threadIdx.x;

    // decode triangular block index: bid -> (bi, bj) with bi >= bj
    int bid = blockIdx.x;
    int bi = (int)((sqrtf(8.f * (float)bid + 1.f) - 1.f) * 0.5f);
    while ((bi + 1) * (bi + 2) / 2 <= bid) bi++;
    while (bi * (bi + 1) / 2 > bid) bi--;
    int bj = bid - bi * (bi + 1) / 2;

    int rowA0 = bi << 7;
    int colB0 = bj << 7;
    int rb = (tid >> 4) << 3;
    int cb = (tid & 15) << 3;

    float acc[8][8];
#pragma unroll
    for (int i = 0; i < 8; i++)
#pragma unroll
        for (int j = 0; j < 8; j++) acc[i][j] = 0.f;

    for (int kt = 0; kt < DD; kt += 16) {
        __syncthreads();
#pragma unroll
        for (int l = 0; l < 2; l++) {
            int f = tid + (l << 8);
            int i = f >> 2;
            int kq = f & 3;
            float4 wa = *(const float4*)(w + kt + (kq << 2));
            float4 va = *(const float4*)(x + (size_t)(rowA0 + i) * DD + kt + (kq << 2));
            float4 vb = *(const float4*)(x + (size_t)(colB0 + i) * DD + kt + (kq << 2));
            As[(kq << 2) + 0][i] = va.x * wa.x;
            As[(kq << 2) + 1][i] = va.y * wa.y;
            As[(kq << 2) + 2][i] = va.z * wa.z;
            As[(kq << 2) + 3][i] = va.w * wa.w;
            Bs[(kq << 2) + 0][i] = vb.x;
            Bs[(kq << 2) + 1][i] = vb.y;
            Bs[(kq << 2) + 2][i] = vb.z;
            Bs[(kq << 2) + 3][i] = vb.w;
        }
        __syncthreads();
#pragma unroll
        for (int k = 0; k < 16; k++) {
            float a[8], b[8];
            *(float4*)(a) = *(const float4*)&As[k][rb];
            *(float4*)(a + 4) = *(const float4*)&As[k][rb + 4];
            *(float4*)(b) = *(const float4*)&Bs[k][cb];
            *(float4*)(b + 4) = *(const float4*)&Bs[k][cb + 4];
#pragma unroll
            for (int i = 0; i < 8; i++)
#pragma unroll
                for (int j = 0; j < 8; j++) acc[i][j] = fmaf(a[i], b[j], acc[i][j]);
        }
    }

    // finalize K values in-place: K = sq_i + sq_j - 2*acc ; diag = 1
#pragma unroll
    for (int ii = 0; ii < 8; ii++) {
        int gi = rowA0 + rb + ii;
        float sqi = __ldg(&g_sq[gi]);
#pragma unroll
        for (int jj = 0; jj < 8; jj++) {
            int gj = colB0 + cb + jj;
            float v = sqi + __ldg(&g_sq[gj]) - 2.f * acc[ii][jj];
            if (gi == gj) v = 1.f;
            acc[ii][jj] = v;
        }
    }

    // primary write: rows gi, cols colB0+cb..+8
#pragma unroll
    for (int ii = 0; ii < 8; ii++) {
        int gi = rowA0 + rb + ii;
        size_t off = (size_t)gi * NN + colB0 + cb;
        float4 lo = make_float4(acc[ii][0], acc[ii][1], acc[ii][2], acc[ii][3]);
        float4 hi = make_float4(acc[ii][4], acc[ii][5], acc[ii][6], acc[ii][7]);
        *(float4*)(g_X0 + off) = lo;
        *(float4*)(g_X0 + off + 4) = hi;
        *(float4*)(g_Ha + off) = lo;
        *(float4*)(g_Ha + off + 4) = hi;
    }

    // mirror write (transposed tile): rows gj, cols rowA0+rb..+8
    if (bi != bj) {
#pragma unroll
        for (int jj = 0; jj < 8; jj++) {
            int gj = colB0 + cb + jj;
            size_t off = (size_t)gj * NN + rowA0 + rb;
            float4 lo = make_float4(acc[0][jj], acc[1][jj], acc[2][jj], acc[3][jj]);
            float4 hi = make_float4(acc[4][jj], acc[5][jj], acc[6][jj], acc[7][jj]);
            *(float4*)(g_X0 + off) = lo;
            *(float4*)(g_X0 + off + 4) = hi;
            *(float4*)(g_Ha + off) = lo;
            *(float4*)(g_Ha + off + 4) = hi;
        }
    }
}

// ---------------- one APPNP hop: O = 0.5 * A_hat * H + 0.5 * X0 ----------------
// DIR == 0: H = g_Ha, O = g_Hb ; DIR == 1: H = g_Hb, O = g_Ha
// Each block handles one row, 2048 columns; each thread: 8 cols as two float4
// streams at c and c+1024 (both fully coalesced per warp).
template <int DIR>
__global__ __launch_bounds__(256) void spmm_kernel() {
    const float* __restrict__ H = DIR ? g_Hb : g_Ha;
    float* __restrict__ O = DIR ? g_Ha : g_Hb;
    int r = blockIdx.x;
    int c = (blockIdx.y << 11) + (threadIdx.x << 2);
    int beg = __ldg(&g_rowptr[r]);
    int end = __ldg(&g_rowptr[r + 1]);

    float4 a0 = make_float4(0.f, 0.f, 0.f, 0.f);
    float4 a1 = make_float4(0.f, 0.f, 0.f, 0.f);

    int e = beg;
    for (; e + 2 <= end; e += 2) {
        int   i0 = __ldg(&g_cols[e]);
        float v0 = __ldg(&g_vals[e]);
        int   i1 = __ldg(&g_cols[e + 1]);
        float v1 = __ldg(&g_vals[e + 1]);
        const float* p0 = H + ((size_t)i0 << 12) + c;
        const float* p1 = H + ((size_t)i1 << 12) + c;
        float4 h00 = __ldg((const float4*)p0);
        float4 h01 = __ldg((const float4*)(p0 + 1024));
        float4 h10 = __ldg((const float4*)p1);
        float4 h11 = __ldg((const float4*)(p1 + 1024));
        a0.x = fmaf(v0, h00.x, a0.x); a0.y = fmaf(v0, h00.y, a0.y);
        a0.z = fmaf(v0, h00.z, a0.z); a0.w = fmaf(v0, h00.w, a0.w);
        a1.x = fmaf(v0, h01.x, a1.x); a1.y = fmaf(v0, h01.y, a1.y);
        a1.z = fmaf(v0, h01.z, a1.z); a1.w = fmaf(v0, h01.w, a1.w);
        a0.x = fmaf(v1, h10.x, a0.x); a0.y = fmaf(v1, h10.y, a0.y);
        a0.z = fmaf(v1, h10.z, a0.z); a0.w = fmaf(v1, h10.w, a0.w);
        a1.x = fmaf(v1, h11.x, a1.x); a1.y = fmaf(v1, h11.y, a1.y);
        a1.z = fmaf(v1, h11.z, a1.z); a1.w = fmaf(v1, h11.w, a1.w);
    }
    if (e < end) {
        int   i0 = __ldg(&g_cols[e]);
        float v0 = __ldg(&g_vals[e]);
        const float* p0 = H + ((size_t)i0 << 12) + c;
        float4 h00 = __ldg((const float4*)p0);
        float4 h01 = __ldg((const float4*)(p0 + 1024));
        a0.x = fmaf(v0, h00.x, a0.x); a0.y = fmaf(v0, h00.y, a0.y);
        a0.z = fmaf(v0, h00.z, a0.z); a0.w = fmaf(v0, h00.w, a0.w);
        a1.x = fmaf(v0, h01.x, a1.x); a1.y = fmaf(v0, h01.y, a1.y);
        a1.z = fmaf(v0, h01.z, a1.z); a1.w = fmaf(v0, h01.w, a1.w);
    }

    size_t ro = ((size_t)r << 12) + c;
    float4 x00 = __ldg((const float4*)(g_X0 + ro));
    float4 x01 = __ldg((const float4*)(g_X0 + ro + 1024));
    float4 o0, o1;
    o0.x = 0.5f * a0.x + 0.5f * x00.x; o0.y = 0.5f * a0.y + 0.5f * x00.y;
    o0.z = 0.5f * a0.z + 0.5f * x00.z; o0.w = 0.5f * a0.w + 0.5f * x00.w;
    o1.x = 0.5f * a1.x + 0.5f * x01.x; o1.y = 0.5f * a1.y + 0.5f * x01.y;
    o1.z = 0.5f * a1.z + 0.5f * x01.z; o1.w = 0.5f * a1.w + 0.5f * x01.w;
    *(float4*)(O + ro) = o0;
    *(float4*)(O + ro + 1024) = o1;
}

// ---------------- transpose g_Ha -> (g_X0 and g_Hb) ----------------
__global__ void transpose_kernel() {
    __shared__ float t[32][33];
    int xi = blockIdx.x * 32 + threadIdx.x;
    int y0 = blockIdx.y * 32;
#pragma unroll
    for (int j = threadIdx.y; j < 32; j += 8)
        t[j][threadIdx.x] = g_Ha[(size_t)(y0 + j) * NN + xi];
    __syncthreads();
    int xo = y0 + threadIdx.x;
    int yo0 = blockIdx.x * 32;
#pragma unroll
    for (int j = threadIdx.y; j < 32; j += 8) {
        float v = t[threadIdx.x][j];
        g_X0[(size_t)(yo0 + j) * NN + xo] = v;
        g_Hb[(size_t)(yo0 + j) * NN + xo] = v;
    }
}

// ---------------- final: out[i,j] = Hb[j,i] ; diag scaled by 1/(deg_row+1) ----------------
__global__ void final_kernel(float* __restrict__ out) {
    __shared__ float t[32][33];
    int xi = blockIdx.x * 32 + threadIdx.x;
    int y0 = blockIdx.y * 32;
#pragma unroll
    for (int j = threadIdx.y; j < 32; j += 8)
        t[j][threadIdx.x] = g_Hb[(size_t)(y0 + j) * NN + xi];
    __syncthreads();
    int b = y0 + threadIdx.x;       // output col
    int a0 = blockIdx.x * 32;       // output row base
#pragma unroll
    for (int j = threadIdx.y; j < 32; j += 8) {
        int a = a0 + j;
        float v = t[threadIdx.x][j]; // = Hb[b][a]
        if (a == b) v *= 1.0f / ((float)g_degrow[a] + 1.0f);
        out[(size_t)a * NN + b] = v;
    }
}

extern "C" void kernel_launch(void* const* d_in, const int* in_sizes, int n_in,
                              void* d_out, int out_size) {
    const float* x = (const float*)d_in[0];
    const float* w = (const float*)d_in[1];
    const int* ei = (const int*)d_in[2];
    const int* src = ei;
    const int* dst = ei + EE;
    float* out = (float*)d_out;

    init_kernel<<<(NN + 255) / 256, 256>>>();
    count_kernel<<<(EE + 255) / 256, 256>>>(src, dst);
    scan_kernel<<<1, 1024>>>();
    fill_kernel<<<(EE + NN + 255) / 256, 256>>>(src, dst);

    sq_kernel<<<NN, 128>>>(x, w);
    gemm_kernel<<<528, 256>>>(x, w);   // lower-triangular tiles only (32*33/2)

    dim3 gs(NN, 2);
    // phase 1: H starts in g_Ha, 10 hops -> result in g_Ha
    for (int h = 0; h < NHOPS; h++) {
        if (h & 1) spmm_kernel<1><<<gs, 256>>>();
        else       spmm_kernel<0><<<gs, 256>>>();
    }

    // X0 = result^T, start buffer g_Hb = result^T
    transpose_kernel<<<dim3(NN / 32, NN / 32), dim3(32, 8)>>>();

    // phase 2: H starts in g_Hb, 10 hops -> result in g_Hb
    for (int h = 0; h < NHOPS; h++) {
        if (h & 1) spmm_kernel<0><<<gs, 256>>>();
        else       spmm_kernel<1><<<gs, 256>>>();
    }

    final_kernel<<<dim3(NN / 32, NN / 32), dim3(32, 8)>>>(out);
    (void)in_sizes; (void)n_in; (void)out_size;
}

// round 4
// speedup vs baseline: 1.6523x; 1.4397x over previous
#include <cuda_runtime.h>
#include <cuda_fp16.h>

#define NN 4096
#define DD 512
#define EE 65536
#define NHOPS 10

// ---------------- static device scratch (allocation-free rule) ----------------
__device__ __half g_X0h[(size_t)NN * NN];  // x0 term for current APPNP phase (fp16)
__device__ __half g_Hah[(size_t)NN * NN];  // ping (fp16)
__device__ __half g_Hbh[(size_t)NN * NN];  // pong (fp16)
__device__ int   g_rowptr[NN + 1];
__device__ int   g_cur[NN];
__device__ int   g_cols[EE + NN];
__device__ float g_vals[EE + NN];
__device__ float g_dis[NN];
__device__ float g_sq[NN];
__device__ int   g_degdst[NN];
__device__ int   g_degrow[NN];

// ---------------- graph preprocessing ----------------
__global__ void init_kernel() {
    int i = blockIdx.x * blockDim.x + threadIdx.x;
    if (i < NN) { g_degdst[i] = 1; g_degrow[i] = 0; }
}

__global__ void count_kernel(const int* __restrict__ src, const int* __restrict__ dst) {
    int i = blockIdx.x * blockDim.x + threadIdx.x;
    if (i < EE) {
        atomicAdd(&g_degdst[dst[i]], 1);
        atomicAdd(&g_degrow[src[i]], 1);
    }
}

// single block, 1024 threads, 4 elements each: exclusive scan of g_degdst -> rowptr
__global__ void scan_kernel() {
    __shared__ int part[1024];
    int t = threadIdx.x;
    int v[4];
    int s = 0;
#pragma unroll
    for (int j = 0; j < 4; j++) { v[j] = g_degdst[t * 4 + j]; s += v[j]; }
    part[t] = s;
    __syncthreads();
    for (int off = 1; off < 1024; off <<= 1) {
        int x = 0;
        if (t >= off) x = part[t - off];
        __syncthreads();
        if (t >= off) part[t] += x;
        __syncthreads();
    }
    int base = part[t] - s; // exclusive
    int run = base;
#pragma unroll
    for (int j = 0; j < 4; j++) {
        int idx = t * 4 + j;
        g_rowptr[idx] = run;
        g_cur[idx] = run;
        g_dis[idx] = rsqrtf((float)v[j]);
        run += v[j];
    }
    if (t == 1023) g_rowptr[NN] = part[1023];
}

__global__ void fill_kernel(const int* __restrict__ src, const int* __restrict__ dst) {
    int i = blockIdx.x * blockDim.x + threadIdx.x;
    if (i < EE) {
        int s = src[i], d = dst[i];
        int p = atomicAdd(&g_cur[d], 1);
        g_cols[p] = s;
        g_vals[p] = g_dis[s] * g_dis[d];
    } else if (i < EE + NN) {
        int n = i - EE;
        int p = atomicAdd(&g_cur[n], 1);
        g_cols[p] = n;
        g_vals[p] = g_dis[n] * g_dis[n];
    }
}

// ---------------- sq[i] = sum_d w_d * x[i,d]^2 ----------------
__global__ void sq_kernel(const float* __restrict__ x, const float* __restrict__ w) {
    __shared__ float red[4];
    int r = blockIdx.x;
    int t = threadIdx.x; // 128
    float s = 0.f;
    for (int d = t; d < DD; d += 128) {
        float xv = x[r * DD + d];
        s += w[d] * xv * xv;
    }
#pragma unroll
    for (int o = 16; o > 0; o >>= 1) s += __shfl_xor_sync(0xffffffffu, s, o);
    if ((t & 31) == 0) red[t >> 5] = s;
    __syncthreads();
    if (t == 0) g_sq[r] = red[0] + red[1] + red[2] + red[3];
}

// ---------------- K = sq_i + sq_j - 2*(x.w) x^T, diag = 1 (SYMMETRIC) ----------------
// Lower-triangular 128x128 tiles only (528 blocks); each tile is written (fp16)
// to g_X0h and g_Hah at (bi,bj) and mirrored (transposed) at (bj,bi).
__global__ __launch_bounds__(256, 2) void gemm_kernel(const float* __restrict__ x,
                                                      const float* __restrict__ w) {
    __shared__ float As[16][132];
    __shared__ float Bs[16][132];
    int tid = threadIdx.x;

    // decode triangular block index: bid -> (bi, bj) with bi >= bj
    int bid = blockIdx.x;
    int bi = (int)((sqrtf(8.f * (float)bid + 1.f) - 1.f) * 0.5f);
    while ((bi + 1) * (bi + 2) / 2 <= bid) bi++;
    while (bi * (bi + 1) / 2 > bid) bi--;
    int bj = bid - bi * (bi + 1) / 2;

    int rowA0 = bi << 7;
    int colB0 = bj << 7;
    int rb = (tid >> 4) << 3;
    int cb = (tid & 15) << 3;

    float acc[8][8];
#pragma unroll
    for (int i = 0; i < 8; i++)
#pragma unroll
        for (int j = 0; j < 8; j++) acc[i][j] = 0.f;

    for (int kt = 0; kt < DD; kt += 16) {
        __syncthreads();
#pragma unroll
        for (int l = 0; l < 2; l++) {
            int f = tid + (l << 8);
            int i = f >> 2;
            int kq = f & 3;
            float4 wa = *(const float4*)(w + kt + (kq << 2));
            float4 va = *(const float4*)(x + (size_t)(rowA0 + i) * DD + kt + (kq << 2));
            float4 vb = *(const float4*)(x + (size_t)(colB0 + i) * DD + kt + (kq << 2));
            As[(kq << 2) + 0][i] = va.x * wa.x;
            As[(kq << 2) + 1][i] = va.y * wa.y;
            As[(kq << 2) + 2][i] = va.z * wa.z;
            As[(kq << 2) + 3][i] = va.w * wa.w;
            Bs[(kq << 2) + 0][i] = vb.x;
            Bs[(kq << 2) + 1][i] = vb.y;
            Bs[(kq << 2) + 2][i] = vb.z;
            Bs[(kq << 2) + 3][i] = vb.w;
        }
        __syncthreads();
#pragma unroll
        for (int k = 0; k < 16; k++) {
            float a[8], b[8];
            *(float4*)(a) = *(const float4*)&As[k][rb];
            *(float4*)(a + 4) = *(const float4*)&As[k][rb + 4];
            *(float4*)(b) = *(const float4*)&Bs[k][cb];
            *(float4*)(b + 4) = *(const float4*)&Bs[k][cb + 4];
#pragma unroll
            for (int i = 0; i < 8; i++)
#pragma unroll
                for (int j = 0; j < 8; j++) acc[i][j] = fmaf(a[i], b[j], acc[i][j]);
        }
    }

    // finalize K in-place: K = sq_i + sq_j - 2*acc ; diag = 1
#pragma unroll
    for (int ii = 0; ii < 8; ii++) {
        int gi = rowA0 + rb + ii;
        float sqi = __ldg(&g_sq[gi]);
#pragma unroll
        for (int jj = 0; jj < 8; jj++) {
            int gj = colB0 + cb + jj;
            float v = sqi + __ldg(&g_sq[gj]) - 2.f * acc[ii][jj];
            if (gi == gj) v = 1.f;
            acc[ii][jj] = v;
        }
    }

    // primary write (fp16): rows gi, cols colB0+cb..+8  (8 halves = 16 B)
#pragma unroll
    for (int ii = 0; ii < 8; ii++) {
        int gi = rowA0 + rb + ii;
        size_t off = (size_t)gi * NN + colB0 + cb;
        __half2 p[4];
#pragma unroll
        for (int q = 0; q < 4; q++)
            p[q] = __floats2half2_rn(acc[ii][2 * q], acc[ii][2 * q + 1]);
        uint4 u = *(uint4*)p;
        *(uint4*)(g_X0h + off) = u;
        *(uint4*)(g_Hah + off) = u;
    }

    // mirror write (transposed tile): rows gj, cols rowA0+rb..+8
    if (bi != bj) {
#pragma unroll
        for (int jj = 0; jj < 8; jj++) {
            int gj = colB0 + cb + jj;
            size_t off = (size_t)gj * NN + rowA0 + rb;
            __half2 p[4];
#pragma unroll
            for (int q = 0; q < 4; q++)
                p[q] = __floats2half2_rn(acc[2 * q][jj], acc[2 * q + 1][jj]);
            uint4 u = *(uint4*)p;
            *(uint4*)(g_X0h + off) = u;
            *(uint4*)(g_Hah + off) = u;
        }
    }
}

// ---------------- one APPNP hop: O = 0.5 * A_hat * H + 0.5 * X0 (fp16 storage) ----------------
// DIR == 0: H = g_Hah, O = g_Hbh ; DIR == 1: H = g_Hbh, O = g_Hah
// Block = one row x 2048 cols; thread = 8 cols = one 16B fp16 gather per neighbor.
#define ACC8(u, v)                                                              \
    {                                                                           \
        __half2* hp_ = (__half2*)&(u);                                          \
        float2 f0_ = __half22float2(hp_[0]);                                    \
        float2 f1_ = __half22float2(hp_[1]);                                    \
        float2 f2_ = __half22float2(hp_[2]);                                    \
        float2 f3_ = __half22float2(hp_[3]);                                    \
        acc[0] = fmaf((v), f0_.x, acc[0]); acc[1] = fmaf((v), f0_.y, acc[1]);   \
        acc[2] = fmaf((v), f1_.x, acc[2]); acc[3] = fmaf((v), f1_.y, acc[3]);   \
        acc[4] = fmaf((v), f2_.x, acc[4]); acc[5] = fmaf((v), f2_.y, acc[5]);   \
        acc[6] = fmaf((v), f3_.x, acc[6]); acc[7] = fmaf((v), f3_.y, acc[7]);   \
    }

template <int DIR>
__global__ __launch_bounds__(256) void spmm_kernel() {
    const __half* __restrict__ H = DIR ? g_Hbh : g_Hah;
    __half* __restrict__ O = DIR ? g_Hah : g_Hbh;
    int r = blockIdx.x;
    int c = (blockIdx.y << 11) + (threadIdx.x << 3);
    int beg = __ldg(&g_rowptr[r]);
    int end = __ldg(&g_rowptr[r + 1]);

    float acc[8];
#pragma unroll
    for (int i = 0; i < 8; i++) acc[i] = 0.f;

    int e = beg;
    for (; e + 4 <= end; e += 4) {
        int   i0 = __ldg(&g_cols[e + 0]);
        int   i1 = __ldg(&g_cols[e + 1]);
        int   i2 = __ldg(&g_cols[e + 2]);
        int   i3 = __ldg(&g_cols[e + 3]);
        float v0 = __ldg(&g_vals[e + 0]);
        float v1 = __ldg(&g_vals[e + 1]);
        float v2 = __ldg(&g_vals[e + 2]);
        float v3 = __ldg(&g_vals[e + 3]);
        uint4 u0 = __ldg((const uint4*)(H + ((size_t)i0 << 12) + c));
        uint4 u1 = __ldg((const uint4*)(H + ((size_t)i1 << 12) + c));
        uint4 u2 = __ldg((const uint4*)(H + ((size_t)i2 << 12) + c));
        uint4 u3 = __ldg((const uint4*)(H + ((size_t)i3 << 12) + c));
        ACC8(u0, v0);
        ACC8(u1, v1);
        ACC8(u2, v2);
        ACC8(u3, v3);
    }
    for (; e < end; e++) {
        int   i0 = __ldg(&g_cols[e]);
        float v0 = __ldg(&g_vals[e]);
        uint4 u0 = __ldg((const uint4*)(H + ((size_t)i0 << 12) + c));
        ACC8(u0, v0);
    }

    size_t ro = ((size_t)r << 12) + c;
    uint4 ux = __ldg((const uint4*)(g_X0h + ro));
    __half2* xp = (__half2*)&ux;
    __half2 o[4];
#pragma unroll
    for (int q = 0; q < 4; q++) {
        float2 xf = __half22float2(xp[q]);
        o[q] = __floats2half2_rn(0.5f * acc[2 * q] + 0.5f * xf.x,
                                 0.5f * acc[2 * q + 1] + 0.5f * xf.y);
    }
    *(uint4*)(O + ro) = *(uint4*)o;
}

// ---------------- transpose g_Hah -> (g_X0h and g_Hbh) ----------------
__global__ void transpose_kernel() {
    __shared__ __half t[32][34];
    int xi = blockIdx.x * 32 + threadIdx.x;
    int y0 = blockIdx.y * 32;
#pragma unroll
    for (int j = threadIdx.y; j < 32; j += 8)
        t[j][threadIdx.x] = g_Hah[(size_t)(y0 + j) * NN + xi];
    __syncthreads();
    int xo = y0 + threadIdx.x;
    int yo0 = blockIdx.x * 32;
#pragma unroll
    for (int j = threadIdx.y; j < 32; j += 8) {
        __half v = t[threadIdx.x][j];
        g_X0h[(size_t)(yo0 + j) * NN + xo] = v;
        g_Hbh[(size_t)(yo0 + j) * NN + xo] = v;
    }
}

// ---------------- final: out[i,j] = Hbh[j,i] ; diag scaled by 1/(deg_row+1) ----------------
__global__ void final_kernel(float* __restrict__ out) {
    __shared__ __half t[32][34];
    int xi = blockIdx.x * 32 + threadIdx.x;
    int y0 = blockIdx.y * 32;
#pragma unroll
    for (int j = threadIdx.y; j < 32; j += 8)
        t[j][threadIdx.x] = g_Hbh[(size_t)(y0 + j) * NN + xi];
    __syncthreads();
    int b = y0 + threadIdx.x;       // output col
    int a0 = blockIdx.x * 32;       // output row base
#pragma unroll
    for (int j = threadIdx.y; j < 32; j += 8) {
        int a = a0 + j;
        float v = __half2float(t[threadIdx.x][j]); // = Hb[b][a]
        if (a == b) v *= 1.0f / ((float)g_degrow[a] + 1.0f);
        out[(size_t)a * NN + b] = v;
    }
}

extern "C" void kernel_launch(void* const* d_in, const int* in_sizes, int n_in,
                              void* d_out, int out_size) {
    const float* x = (const float*)d_in[0];
    const float* w = (const float*)d_in[1];
    const int* ei = (const int*)d_in[2];
    const int* src = ei;
    const int* dst = ei + EE;
    float* out = (float*)d_out;

    init_kernel<<<(NN + 255) / 256, 256>>>();
    count_kernel<<<(EE + 255) / 256, 256>>>(src, dst);
    scan_kernel<<<1, 1024>>>();
    fill_kernel<<<(EE + NN + 255) / 256, 256>>>(src, dst);

    sq_kernel<<<NN, 128>>>(x, w);
    gemm_kernel<<<528, 256>>>(x, w);   // lower-triangular tiles only (32*33/2)

    dim3 gs(NN, 2);
    // phase 1: H starts in g_Hah, 10 hops -> result in g_Hah
    for (int h = 0; h < NHOPS; h++) {
        if (h & 1) spmm_kernel<1><<<gs, 256>>>();
        else       spmm_kernel<0><<<gs, 256>>>();
    }

    // X0 = result^T, start buffer g_Hbh = result^T
    transpose_kernel<<<dim3(NN / 32, NN / 32), dim3(32, 8)>>>();

    // phase 2: H starts in g_Hbh, 10 hops -> result in g_Hbh
    for (int h = 0; h < NHOPS; h++) {
        if (h & 1) spmm_kernel<0><<<gs, 256>>>();
        else       spmm_kernel<1><<<gs, 256>>>();
    }

    final_kernel<<<dim3(NN / 32, NN / 32), dim3(32, 8)>>>(out);
    (void)in_sizes; (void)n_in; (void)out_size;
}

// round 6
// speedup vs baseline: 1.8569x; 1.1238x over previous
#include <cuda_runtime.h>
#include <cuda_fp16.h>
#include <mma.h>

using namespace nvcuda;

#define NN 4096
#define DD 512
#define EE 65536
#define NHOPS 10

// ---------------- static device scratch (allocation-free rule) ----------------
__device__ __half g_X0h[(size_t)NN * NN];  // x0 term for current APPNP phase (fp16)
__device__ __half g_Hah[(size_t)NN * NN];  // ping (fp16)
__device__ __half g_Hbh[(size_t)NN * NN];  // pong (fp16)
__device__ __half g_xh[(size_t)NN * DD];   // x in fp16
__device__ __half g_xwh[(size_t)NN * DD];  // x*w in fp16
__device__ int   g_rowptr[NN + 1];
__device__ int   g_cur[NN];
__device__ int   g_cols[EE + NN];
__device__ float g_vals[EE + NN];
__device__ float g_dis[NN];
__device__ float g_sq[NN];
__device__ int   g_degdst[NN];
__device__ int   g_degrow[NN];

// ---------------- graph preprocessing ----------------
__global__ void init_kernel() {
    int i = blockIdx.x * blockDim.x + threadIdx.x;
    if (i < NN) { g_degdst[i] = 1; g_degrow[i] = 0; }
}

__global__ void count_kernel(const int* __restrict__ src, const int* __restrict__ dst) {
    int i = blockIdx.x * blockDim.x + threadIdx.x;
    if (i < EE) {
        atomicAdd(&g_degdst[dst[i]], 1);
        atomicAdd(&g_degrow[src[i]], 1);
    }
}

// single block, 1024 threads, 4 elements each: exclusive scan of g_degdst -> rowptr
__global__ void scan_kernel() {
    __shared__ int part[1024];
    int t = threadIdx.x;
    int v[4];
    int s = 0;
#pragma unroll
    for (int j = 0; j < 4; j++) { v[j] = g_degdst[t * 4 + j]; s += v[j]; }
    part[t] = s;
    __syncthreads();
    for (int off = 1; off < 1024; off <<= 1) {
        int x = 0;
        if (t >= off) x = part[t - off];
        __syncthreads();
        if (t >= off) part[t] += x;
        __syncthreads();
    }
    int base = part[t] - s; // exclusive
    int run = base;
#pragma unroll
    for (int j = 0; j < 4; j++) {
        int idx = t * 4 + j;
        g_rowptr[idx] = run;
        g_cur[idx] = run;
        g_dis[idx] = rsqrtf((float)v[j]);
        run += v[j];
    }
    if (t == 1023) g_rowptr[NN] = part[1023];
}

__global__ void fill_kernel(const int* __restrict__ src, const int* __restrict__ dst) {
    int i = blockIdx.x * blockDim.x + threadIdx.x;
    if (i < EE) {
        int s = src[i], d = dst[i];
        int p = atomicAdd(&g_cur[d], 1);
        g_cols[p] = s;
        g_vals[p] = g_dis[s] * g_dis[d];
    } else if (i < EE + NN) {
        int n = i - EE;
        int p = atomicAdd(&g_cur[n], 1);
        g_cols[p] = n;
        g_vals[p] = g_dis[n] * g_dis[n];
    }
}

// ---------------- sq[i] = sum_d w_d * x[i,d]^2  (fp32) + fp16 conversions ----------------
__global__ void sq_kernel(const float* __restrict__ x, const float* __restrict__ w) {
    __shared__ float red[4];
    int r = blockIdx.x;
    int t = threadIdx.x; // 128
    float s = 0.f;
    for (int d = t; d < DD; d += 128) {
        float xv = x[r * DD + d];
        float wv = w[d];
        s += wv * xv * xv;
        g_xh[(size_t)r * DD + d] = __float2half_rn(xv);
        g_xwh[(size_t)r * DD + d] = __float2half_rn(xv * wv);
    }
#pragma unroll
    for (int o = 16; o > 0; o >>= 1) s += __shfl_xor_sync(0xffffffffu, s, o);
    if ((t & 31) == 0) red[t >> 5] = s;
    __syncthreads();
    if (t == 0) g_sq[r] = red[0] + red[1] + red[2] + red[3];
}

// ---------------- K = sq_i + sq_j - 2*(x.w) x^T, diag = 1 (SYMMETRIC, HMMA) ----------------
// Lower-triangular 128x128 tiles (528 blocks), fp16 wmma with fp32 accum.
// 8 warps: warp_m = wid>>1 (0..3), warp_n = wid&1 (0..1); warp tile 32x64.
// NOTE: epilogue staging tile ld MUST be a multiple of 4 floats (16 B) for
// wmma::store_matrix_sync — use 136.
#define TLD 136
__global__ __launch_bounds__(256, 1) void gemm_kernel() {
    __shared__ float tile[64][TLD];
    int tid = threadIdx.x;
    int wid = tid >> 5;
    int warp_m = wid >> 1;
    int warp_n = wid & 1;

    // decode triangular block index: bid -> (bi, bj) with bi >= bj
    int bid = blockIdx.x;
    int bi = (int)((sqrtf(8.f * (float)bid + 1.f) - 1.f) * 0.5f);
    while ((bi + 1) * (bi + 2) / 2 <= bid) bi++;
    while (bi * (bi + 1) / 2 > bid) bi--;
    int bj = bid - bi * (bi + 1) / 2;

    int rowA0 = bi << 7;
    int colB0 = bj << 7;

    wmma::fragment<wmma::accumulator, 16, 16, 16, float> c[2][4];
#pragma unroll
    for (int mi = 0; mi < 2; mi++)
#pragma unroll
        for (int ni = 0; ni < 4; ni++) wmma::fill_fragment(c[mi][ni], 0.f);

    const __half* Abase = g_xwh + (size_t)(rowA0 + warp_m * 32) * DD;
    const __half* Bbase = g_xh + (size_t)(colB0 + warp_n * 64) * DD;

    for (int k = 0; k < DD; k += 16) {
        wmma::fragment<wmma::matrix_a, 16, 16, 16, __half, wmma::row_major> a[2];
        wmma::fragment<wmma::matrix_b, 16, 16, 16, __half, wmma::col_major> b[4];
#pragma unroll
        for (int mi = 0; mi < 2; mi++)
            wmma::load_matrix_sync(a[mi], Abase + (size_t)(mi * 16) * DD + k, DD);
#pragma unroll
        for (int ni = 0; ni < 4; ni++)
            wmma::load_matrix_sync(b[ni], Bbase + (size_t)(ni * 16) * DD + k, DD);
#pragma unroll
        for (int mi = 0; mi < 2; mi++)
#pragma unroll
            for (int ni = 0; ni < 4; ni++)
                wmma::mma_sync(c[mi][ni], a[mi], b[ni], c[mi][ni]);
    }

    // epilogue in two 64-row phases through smem
    for (int p = 0; p < 2; p++) {
        __syncthreads();
        if ((warp_m >> 1) == p) {
            int lm = (warp_m & 1) * 32;
#pragma unroll
            for (int mi = 0; mi < 2; mi++)
#pragma unroll
                for (int ni = 0; ni < 4; ni++)
                    wmma::store_matrix_sync(&tile[lm + mi * 16][warp_n * 64 + ni * 16],
                                            c[mi][ni], TLD, wmma::mem_row_major);
        }
        __syncthreads();

        int row0 = rowA0 + p * 64;

        // primary write: rows (row0+li), cols colB0+lj..+8
        {
            int lj = (tid & 15) << 3;
#pragma unroll
            for (int q = 0; q < 4; q++) {
                int li = (tid >> 4) + q * 16;
                int gi = row0 + li;
                float sqi = __ldg(&g_sq[gi]);
                __half2 pk[4];
#pragma unroll
                for (int h2 = 0; h2 < 4; h2++) {
                    int gj0 = colB0 + lj + 2 * h2;
                    float v0 = sqi + __ldg(&g_sq[gj0]) - 2.f * tile[li][lj + 2 * h2];
                    float v1 = sqi + __ldg(&g_sq[gj0 + 1]) - 2.f * tile[li][lj + 2 * h2 + 1];
                    if (gi == gj0) v0 = 1.f;
                    if (gi == gj0 + 1) v1 = 1.f;
                    pk[h2] = __floats2half2_rn(v0, v1);
                }
                size_t off = (size_t)gi * NN + colB0 + lj;
                uint4 u = *(uint4*)pk;
                *(uint4*)(g_X0h + off) = u;
                *(uint4*)(g_Hah + off) = u;
            }
        }

        // mirror write (transposed): rows colB0+jm, cols row0+im..+8
        if (bi != bj) {
            int im = (tid & 7) << 3;
#pragma unroll
            for (int q = 0; q < 4; q++) {
                int jm = (tid >> 3) + q * 32;
                int gj = colB0 + jm;
                float sqj = __ldg(&g_sq[gj]);
                __half2 pk[4];
#pragma unroll
                for (int h2 = 0; h2 < 4; h2++) {
                    int gi0 = row0 + im + 2 * h2;
                    float v0 = sqj + __ldg(&g_sq[gi0]) - 2.f * tile[im + 2 * h2][jm];
                    float v1 = sqj + __ldg(&g_sq[gi0 + 1]) - 2.f * tile[im + 2 * h2 + 1][jm];
                    pk[h2] = __floats2half2_rn(v0, v1);
                }
                size_t off = (size_t)gj * NN + row0 + im;
                uint4 u = *(uint4*)pk;
                *(uint4*)(g_X0h + off) = u;
                *(uint4*)(g_Hah + off) = u;
            }
        }
    }
}

// ---------------- one APPNP hop: O = 0.5 * A_hat * H + 0.5 * X0 (fp16 storage) ----------------
#define ACC8(u, v)                                                              \
    {                                                                           \
        __half2* hp_ = (__half2*)&(u);                                          \
        float2 f0_ = __half22float2(hp_[0]);                                    \
        float2 f1_ = __half22float2(hp_[1]);                                    \
        float2 f2_ = __half22float2(hp_[2]);                                    \
        float2 f3_ = __half22float2(hp_[3]);                                    \
        acc[0] = fmaf((v), f0_.x, acc[0]); acc[1] = fmaf((v), f0_.y, acc[1]);   \
        acc[2] = fmaf((v), f1_.x, acc[2]); acc[3] = fmaf((v), f1_.y, acc[3]);   \
        acc[4] = fmaf((v), f2_.x, acc[4]); acc[5] = fmaf((v), f2_.y, acc[5]);   \
        acc[6] = fmaf((v), f3_.x, acc[6]); acc[7] = fmaf((v), f3_.y, acc[7]);   \
    }

template <int DIR>
__global__ __launch_bounds__(256) void spmm_kernel() {
    const __half* __restrict__ H = DIR ? g_Hbh : g_Hah;
    __half* __restrict__ O = DIR ? g_Hah : g_Hbh;
    int r = blockIdx.x;
    int c = (blockIdx.y << 11) + (threadIdx.x << 3);
    int beg = __ldg(&g_rowptr[r]);
    int end = __ldg(&g_rowptr[r + 1]);

    float acc[8];
#pragma unroll
    for (int i = 0; i < 8; i++) acc[i] = 0.f;

    int e = beg;
    for (; e + 4 <= end; e += 4) {
        int   i0 = __ldg(&g_cols[e + 0]);
        int   i1 = __ldg(&g_cols[e + 1]);
        int   i2 = __ldg(&g_cols[e + 2]);
        int   i3 = __ldg(&g_cols[e + 3]);
        float v0 = __ldg(&g_vals[e + 0]);
        float v1 = __ldg(&g_vals[e + 1]);
        float v2 = __ldg(&g_vals[e + 2]);
        float v3 = __ldg(&g_vals[e + 3]);
        uint4 u0 = __ldg((const uint4*)(H + ((size_t)i0 << 12) + c));
        uint4 u1 = __ldg((const uint4*)(H + ((size_t)i1 << 12) + c));
        uint4 u2 = __ldg((const uint4*)(H + ((size_t)i2 << 12) + c));
        uint4 u3 = __ldg((const uint4*)(H + ((size_t)i3 << 12) + c));
        ACC8(u0, v0);
        ACC8(u1, v1);
        ACC8(u2, v2);
        ACC8(u3, v3);
    }
    for (; e < end; e++) {
        int   i0 = __ldg(&g_cols[e]);
        float v0 = __ldg(&g_vals[e]);
        uint4 u0 = __ldg((const uint4*)(H + ((size_t)i0 << 12) + c));
        ACC8(u0, v0);
    }

    size_t ro = ((size_t)r << 12) + c;
    uint4 ux = __ldg((const uint4*)(g_X0h + ro));
    __half2* xp = (__half2*)&ux;
    __half2 o[4];
#pragma unroll
    for (int q = 0; q < 4; q++) {
        float2 xf = __half22float2(xp[q]);
        o[q] = __floats2half2_rn(0.5f * acc[2 * q] + 0.5f * xf.x,
                                 0.5f * acc[2 * q + 1] + 0.5f * xf.y);
    }
    *(uint4*)(O + ro) = *(uint4*)o;
}

// ---------------- transpose g_Hah -> (g_X0h and g_Hbh) ----------------
__global__ void transpose_kernel() {
    __shared__ __half t[32][34];
    int xi = blockIdx.x * 32 + threadIdx.x;
    int y0 = blockIdx.y * 32;
#pragma unroll
    for (int j = threadIdx.y; j < 32; j += 8)
        t[j][threadIdx.x] = g_Hah[(size_t)(y0 + j) * NN + xi];
    __syncthreads();
    int xo = y0 + threadIdx.x;
    int yo0 = blockIdx.x * 32;
#pragma unroll
    for (int j = threadIdx.y; j < 32; j += 8) {
        __half v = t[threadIdx.x][j];
        g_X0h[(size_t)(yo0 + j) * NN + xo] = v;
        g_Hbh[(size_t)(yo0 + j) * NN + xo] = v;
    }
}

// ---------------- final: out[i,j] = Hbh[j,i] ; diag scaled by 1/(deg_row+1) ----------------
__global__ void final_kernel(float* __restrict__ out) {
    __shared__ __half t[32][34];
    int xi = blockIdx.x * 32 + threadIdx.x;
    int y0 = blockIdx.y * 32;
#pragma unroll
    for (int j = threadIdx.y; j < 32; j += 8)
        t[j][threadIdx.x] = g_Hbh[(size_t)(y0 + j) * NN + xi];
    __syncthreads();
    int b = y0 + threadIdx.x;       // output col
    int a0 = blockIdx.x * 32;       // output row base
#pragma unroll
    for (int j = threadIdx.y; j < 32; j += 8) {
        int a = a0 + j;
        float v = __half2float(t[threadIdx.x][j]); // = Hb[b][a]
        if (a == b) v *= 1.0f / ((float)g_degrow[a] + 1.0f);
        out[(size_t)a * NN + b] = v;
    }
}

extern "C" void kernel_launch(void* const* d_in, const int* in_sizes, int n_in,
                              void* d_out, int out_size) {
    const float* x = (const float*)d_in[0];
    const float* w = (const float*)d_in[1];
    const int* ei = (const int*)d_in[2];
    const int* src = ei;
    const int* dst = ei + EE;
    float* out = (float*)d_out;

    init_kernel<<<(NN + 255) / 256, 256>>>();
    count_kernel<<<(EE + 255) / 256, 256>>>(src, dst);
    scan_kernel<<<1, 1024>>>();
    fill_kernel<<<(EE + NN + 255) / 256, 256>>>(src, dst);

    sq_kernel<<<NN, 128>>>(x, w);
    gemm_kernel<<<528, 256>>>();   // lower-triangular tiles only (32*33/2)

    dim3 gs(NN, 2);
    // phase 1: H starts in g_Hah, 10 hops -> result in g_Hah
    for (int h = 0; h < NHOPS; h++) {
        if (h & 1) spmm_kernel<1><<<gs, 256>>>();
        else       spmm_kernel<0><<<gs, 256>>>();
    }

    // X0 = result^T, start buffer g_Hbh = result^T
    transpose_kernel<<<dim3(NN / 32, NN / 32), dim3(32, 8)>>>();

    // phase 2: H starts in g_Hbh, 10 hops -> result in g_Hbh
    for (int h = 0; h < NHOPS; h++) {
        if (h & 1) spmm_kernel<0><<<gs, 256>>>();
        else       spmm_kernel<1><<<gs, 256>>>();
    }

    final_kernel<<<dim3(NN / 32, NN / 32), dim3(32, 8)>>>(out);
    (void)in_sizes; (void)n_in; (void)out_size;
}

// round 7
// speedup vs baseline: 2.2274x; 1.1995x over previous
#include <cuda_runtime.h>
#include <cuda_fp16.h>
#include <mma.h>

using namespace nvcuda;

#define NN 4096
#define DD 512
#define EE 65536

// ---------------- static device scratch (allocation-free rule) ----------------
__device__ __half g_Hah[(size_t)NN * NN];     // P ping
__device__ __half g_Hbh[(size_t)NN * NN];     // P pong (final P lands here)
__device__ __half g_Y0[(size_t)NN * 1024];    // [X | Xw] fp16
__device__ __half g_Ya[(size_t)NN * 1024];    // thin ping / final -2*pX
__device__ __half g_Yb[(size_t)NN * 1024];    // thin pong (final [pX | pXw])
__device__ float g_a[NN];                     // P*u
__device__ float g_b[NN];                     // P*1
__device__ int   g_rowptr[NN + 1];
__device__ int   g_cur[NN];
__device__ int   g_cols[EE + NN];
__device__ float g_vals[EE + NN];
__device__ float g_dis[NN];
__device__ float g_sq[NN];
__device__ int   g_degdst[NN];
__device__ int   g_degrow[NN];

// ---------------- graph preprocessing ----------------
__global__ void init_kernel() {
    int i = blockIdx.x * blockDim.x + threadIdx.x;
    if (i < NN) { g_degdst[i] = 1; g_degrow[i] = 0; }
}

__global__ void count_kernel(const int* __restrict__ src, const int* __restrict__ dst) {
    int i = blockIdx.x * blockDim.x + threadIdx.x;
    if (i < EE) {
        atomicAdd(&g_degdst[dst[i]], 1);
        atomicAdd(&g_degrow[src[i]], 1);
    }
}

// single block, 1024 threads, 4 elements each: exclusive scan of g_degdst -> rowptr
__global__ void scan_kernel() {
    __shared__ int part[1024];
    int t = threadIdx.x;
    int v[4];
    int s = 0;
#pragma unroll
    for (int j = 0; j < 4; j++) { v[j] = g_degdst[t * 4 + j]; s += v[j]; }
    part[t] = s;
    __syncthreads();
    for (int off = 1; off < 1024; off <<= 1) {
        int x = 0;
        if (t >= off) x = part[t - off];
        __syncthreads();
        if (t >= off) part[t] += x;
        __syncthreads();
    }
    int base = part[t] - s; // exclusive
    int run = base;
#pragma unroll
    for (int j = 0; j < 4; j++) {
        int idx = t * 4 + j;
        g_rowptr[idx] = run;
        g_cur[idx] = run;
        g_dis[idx] = rsqrtf((float)v[j]);
        run += v[j];
    }
    if (t == 1023) g_rowptr[NN] = part[1023];
}

__global__ void fill_kernel(const int* __restrict__ src, const int* __restrict__ dst) {
    int i = blockIdx.x * blockDim.x + threadIdx.x;
    if (i < EE) {
        int s = src[i], d = dst[i];
        int p = atomicAdd(&g_cur[d], 1);
        g_cols[p] = s;
        g_vals[p] = g_dis[s] * g_dis[d];
    } else if (i < EE + NN) {
        int n = i - EE;
        int p = atomicAdd(&g_cur[n], 1);
        g_cols[p] = n;
        g_vals[p] = g_dis[n] * g_dis[n];
    }
}

// ---------------- sq[i] = sum_d w_d * x[i,d]^2 ; build Y0 = [X | Xw] fp16 ----------------
__global__ void sq_kernel(const float* __restrict__ x, const float* __restrict__ w) {
    __shared__ float red[4];
    int r = blockIdx.x;
    int t = threadIdx.x; // 128
    float s = 0.f;
    for (int d = t; d < DD; d += 128) {
        float xv = x[r * DD + d];
        float wv = w[d];
        s += wv * xv * xv;
        g_Y0[(size_t)r * 1024 + d] = __float2half_rn(xv);
        g_Y0[(size_t)r * 1024 + 512 + d] = __float2half_rn(xv * wv);
    }
#pragma unroll
    for (int o = 16; o > 0; o >>= 1) s += __shfl_xor_sync(0xffffffffu, s, o);
    if ((t & 31) == 0) red[t >> 5] = s;
    __syncthreads();
    if (t == 0) g_sq[r] = red[0] + red[1] + red[2] + red[3];
}

// ---------------- P1 = 0.5*Ahat + 0.5*I  (dense fp16 in g_Hah) ----------------
__global__ void p1_init_kernel() {
    int r = blockIdx.x;
    int c = (blockIdx.y << 11) + (threadIdx.x << 3);
    uint4 z = make_uint4(0u, 0u, 0u, 0u);
    *(uint4*)(g_Hah + (size_t)r * NN + c) = z;
    if (r >= c && r < c + 8) g_Hah[(size_t)r * NN + r] = __float2half_rn(0.5f);
}

__global__ void p1_scatter_kernel(const int* __restrict__ src, const int* __restrict__ dst) {
    int i = blockIdx.x * blockDim.x + threadIdx.x;
    if (i < EE) {
        int s = src[i], d = dst[i];
        atomicAdd(&g_Hah[(size_t)d * NN + s], __float2half_rn(0.5f * g_dis[s] * g_dis[d]));
    } else if (i < EE + NN) {
        int n = i - EE;
        atomicAdd(&g_Hah[(size_t)n * NN + n], __float2half_rn(0.5f * g_dis[n] * g_dis[n]));
    }
}

// ---------------- accumulate helper ----------------
#define ACC8(u, v)                                                              \
    {                                                                           \
        __half2* hp_ = (__half2*)&(u);                                          \
        float2 f0_ = __half22float2(hp_[0]);                                    \
        float2 f1_ = __half22float2(hp_[1]);                                    \
        float2 f2_ = __half22float2(hp_[2]);                                    \
        float2 f3_ = __half22float2(hp_[3]);                                    \
        acc[0] = fmaf((v), f0_.x, acc[0]); acc[1] = fmaf((v), f0_.y, acc[1]);   \
        acc[2] = fmaf((v), f1_.x, acc[2]); acc[3] = fmaf((v), f1_.y, acc[3]);   \
        acc[4] = fmaf((v), f2_.x, acc[4]); acc[5] = fmaf((v), f2_.y, acc[5]);   \
        acc[6] = fmaf((v), f3_.x, acc[6]); acc[7] = fmaf((v), f3_.y, acc[7]);   \
    }

// ---------------- one P-build hop: O = 0.5 * Ahat * H + 0.5 * I ----------------
// DIR == 0: H = g_Hah, O = g_Hbh ; DIR == 1: H = g_Hbh, O = g_Hah
template <int DIR>
__global__ __launch_bounds__(256) void phop_kernel() {
    const __half* __restrict__ H = DIR ? g_Hbh : g_Hah;
    __half* __restrict__ O = DIR ? g_Hah : g_Hbh;
    int r = blockIdx.x;
    int c = (blockIdx.y << 11) + (threadIdx.x << 3);
    int beg = __ldg(&g_rowptr[r]);
    int end = __ldg(&g_rowptr[r + 1]);

    float acc[8];
#pragma unroll
    for (int i = 0; i < 8; i++) acc[i] = 0.f;

    int e = beg;
    for (; e + 4 <= end; e += 4) {
        int   i0 = __ldg(&g_cols[e + 0]);
        int   i1 = __ldg(&g_cols[e + 1]);
        int   i2 = __ldg(&g_cols[e + 2]);
        int   i3 = __ldg(&g_cols[e + 3]);
        float v0 = __ldg(&g_vals[e + 0]);
        float v1 = __ldg(&g_vals[e + 1]);
        float v2 = __ldg(&g_vals[e + 2]);
        float v3 = __ldg(&g_vals[e + 3]);
        uint4 u0 = __ldg((const uint4*)(H + ((size_t)i0 << 12) + c));
        uint4 u1 = __ldg((const uint4*)(H + ((size_t)i1 << 12) + c));
        uint4 u2 = __ldg((const uint4*)(H + ((size_t)i2 << 12) + c));
        uint4 u3 = __ldg((const uint4*)(H + ((size_t)i3 << 12) + c));
        ACC8(u0, v0);
        ACC8(u1, v1);
        ACC8(u2, v2);
        ACC8(u3, v3);
    }
    for (; e < end; e++) {
        int   i0 = __ldg(&g_cols[e]);
        float v0 = __ldg(&g_vals[e]);
        uint4 u0 = __ldg((const uint4*)(H + ((size_t)i0 << 12) + c));
        ACC8(u0, v0);
    }

    int dr = r - c; // diag element index within this thread's 8 columns, if 0..7
    __half2 o[4];
#pragma unroll
    for (int q = 0; q < 4; q++) {
        float f0 = 0.5f * acc[2 * q];
        float f1 = 0.5f * acc[2 * q + 1];
        if (dr == 2 * q) f0 += 0.5f;
        if (dr == 2 * q + 1) f1 += 0.5f;
        o[q] = __floats2half2_rn(f0, f1);
    }
    *(uint4*)(O + ((size_t)r << 12) + c) = *(uint4*)o;
}

// ---------------- one thin hop on Y (1024 cols): O = 0.5 * Ahat * H + 0.5 * Y0 ----------------
// S == 0: Y0 -> Ya ; S == 1: Ya -> Yb ; S == 2: Yb -> Ya
template <int S>
__global__ __launch_bounds__(128) void thop_kernel() {
    const __half* __restrict__ H = (S == 0) ? g_Y0 : ((S == 1) ? g_Ya : g_Yb);
    __half* __restrict__ O = (S == 0) ? g_Ya : ((S == 1) ? g_Yb : g_Ya);
    int r = blockIdx.x;
    int c = threadIdx.x << 3; // 128 * 8 = 1024
    int beg = __ldg(&g_rowptr[r]);
    int end = __ldg(&g_rowptr[r + 1]);

    float acc[8];
#pragma unroll
    for (int i = 0; i < 8; i++) acc[i] = 0.f;

    int e = beg;
    for (; e + 4 <= end; e += 4) {
        int   i0 = __ldg(&g_cols[e + 0]);
        int   i1 = __ldg(&g_cols[e + 1]);
        int   i2 = __ldg(&g_cols[e + 2]);
        int   i3 = __ldg(&g_cols[e + 3]);
        float v0 = __ldg(&g_vals[e + 0]);
        float v1 = __ldg(&g_vals[e + 1]);
        float v2 = __ldg(&g_vals[e + 2]);
        float v3 = __ldg(&g_vals[e + 3]);
        uint4 u0 = __ldg((const uint4*)(H + ((size_t)i0 << 10) + c));
        uint4 u1 = __ldg((const uint4*)(H + ((size_t)i1 << 10) + c));
        uint4 u2 = __ldg((const uint4*)(H + ((size_t)i2 << 10) + c));
        uint4 u3 = __ldg((const uint4*)(H + ((size_t)i3 << 10) + c));
        ACC8(u0, v0);
        ACC8(u1, v1);
        ACC8(u2, v2);
        ACC8(u3, v3);
    }
    for (; e < end; e++) {
        int   i0 = __ldg(&g_cols[e]);
        float v0 = __ldg(&g_vals[e]);
        uint4 u0 = __ldg((const uint4*)(H + ((size_t)i0 << 10) + c));
        ACC8(u0, v0);
    }

    uint4 ux = __ldg((const uint4*)(g_Y0 + ((size_t)r << 10) + c));
    __half2* xp = (__half2*)&ux;
    __half2 o[4];
#pragma unroll
    for (int q = 0; q < 4; q++) {
        float2 xf = __half22float2(xp[q]);
        o[q] = __floats2half2_rn(0.5f * acc[2 * q] + 0.5f * xf.x,
                                 0.5f * acc[2 * q + 1] + 0.5f * xf.y);
    }
    *(uint4*)(O + ((size_t)r << 10) + c) = *(uint4*)o;
}

// ---------------- prescale: Ya[:, 0:512] = -2 * Yb[:, 0:512]  (pX -> -2*pX) ----------------
__global__ void prescale_kernel() {
    int r = blockIdx.x;
    int c = threadIdx.x << 3; // 64 * 8 = 512
    uint4 u = *(const uint4*)(g_Yb + ((size_t)r << 10) + c);
    __half2* hp = (__half2*)&u;
    __half2 m2 = __floats2half2_rn(-2.f, -2.f);
#pragma unroll
    for (int q = 0; q < 4; q++) hp[q] = __hmul2(hp[q], m2);
    *(uint4*)(g_Ya + ((size_t)r << 10) + c) = u;
}

// ---------------- a = P*u, b = P*1 (warp per row over P = g_Hbh) ----------------
__global__ __launch_bounds__(256) void matvec_kernel() {
    int lane = threadIdx.x & 31;
    int wid = threadIdx.x >> 5;
    int r = blockIdx.x * 8 + wid;
    const __half* Pr = g_Hbh + ((size_t)r << 12);
    float sa = 0.f, sb = 0.f;
    for (int t = lane; t < NN / 8; t += 32) {
        uint4 u = __ldg((const uint4*)(Pr + t * 8));
        __half2* hp = (__half2*)&u;
        float4 w0 = __ldg((const float4*)(g_sq + t * 8));
        float4 w1 = __ldg((const float4*)(g_sq + t * 8 + 4));
        float2 f0 = __half22float2(hp[0]);
        float2 f1 = __half22float2(hp[1]);
        float2 f2 = __half22float2(hp[2]);
        float2 f3 = __half22float2(hp[3]);
        sa += f0.x * w0.x + f0.y * w0.y + f1.x * w0.z + f1.y * w0.w
            + f2.x * w1.x + f2.y * w1.y + f3.x * w1.z + f3.y * w1.w;
        sb += f0.x + f0.y + f1.x + f1.y + f2.x + f2.y + f3.x + f3.y;
    }
#pragma unroll
    for (int o = 16; o > 0; o >>= 1) {
        sa += __shfl_xor_sync(0xffffffffu, sa, o);
        sb += __shfl_xor_sync(0xffffffffu, sb, o);
    }
    if (lane == 0) { g_a[r] = sa; g_b[r] = sb; }
}

// ---------------- fused final GEMM ----------------
// out = P*P^T - 2*(pXw)(pX)^T + a*b^T + b*a^T, diag /(deg_row+1).
// Lower-triangular 128x128 tiles (528 blocks) + transposed mirror.
// cp.async double-buffered smem staging, wmma fp16 -> fp32.
#define GKT 32
#define GP 40     // smem pitch (halves)
#define EPLD 136  // epilogue float pitch (mult of 4)

__global__ __launch_bounds__(256) void final_gemm_kernel(float* __restrict__ out) {
    __shared__ alignas(16) unsigned char sraw[2 * 128 * GP * 2 * 2]; // 40960 B
    __half* As = (__half*)sraw;                    // [2][128][GP]
    __half* Bs = (__half*)(sraw + 2 * 128 * GP * 2);
    float* ep = (float*)sraw;                      // epilogue reuse (34816 B)

    int tid = threadIdx.x;
    int wid = tid >> 5;
    int warp_m = wid >> 1;
    int warp_n = wid & 1;

    int bid = blockIdx.x;
    int bi = (int)((sqrtf(8.f * (float)bid + 1.f) - 1.f) * 0.5f);
    while ((bi + 1) * (bi + 2) / 2 <= bid) bi++;
    while (bi * (bi + 1) / 2 > bid) bi--;
    int bj = bid - bi * (bi + 1) / 2;
    int i0 = bi << 7;
    int j0 = bj << 7;

    wmma::fragment<wmma::accumulator, 16, 16, 16, float> c[2][4];
#pragma unroll
    for (int mi = 0; mi < 2; mi++)
#pragma unroll
        for (int ni = 0; ni < 4; ni++) wmma::fill_fragment(c[mi][ni], 0.f);

    auto stage = [&](int buf, const __half* bA, const __half* bB, int ldx, int k0) {
#pragma unroll
        for (int j = 0; j < 2; j++) {
            int idx = tid * 2 + j;
            int row = idx >> 2;
            int kq = idx & 3;
            const __half* ga = bA + (size_t)row * ldx + k0 + kq * 8;
            const __half* gb = bB + (size_t)row * ldx + k0 + kq * 8;
            unsigned int sa = (unsigned int)__cvta_generic_to_shared(As + buf * 128 * GP + row * GP + kq * 8);
            unsigned int sb = (unsigned int)__cvta_generic_to_shared(Bs + buf * 128 * GP + row * GP + kq * 8);
            asm volatile("cp.async.ca.shared.global [%0], [%1], 16;\n" ::"r"(sa), "l"(ga) : "memory");
            asm volatile("cp.async.ca.shared.global [%0], [%1], 16;\n" ::"r"(sb), "l"(gb) : "memory");
        }
        asm volatile("cp.async.commit_group;\n" ::: "memory");
    };

    auto compute = [&](int buf) {
#pragma unroll
        for (int kk = 0; kk < GKT; kk += 16) {
            wmma::fragment<wmma::matrix_a, 16, 16, 16, __half, wmma::row_major> af[2];
            wmma::fragment<wmma::matrix_b, 16, 16, 16, __half, wmma::col_major> bf[4];
#pragma unroll
            for (int mi = 0; mi < 2; mi++)
                wmma::load_matrix_sync(af[mi], As + buf * 128 * GP + (warp_m * 32 + mi * 16) * GP + kk, GP);
#pragma unroll
            for (int ni = 0; ni < 4; ni++)
                wmma::load_matrix_sync(bf[ni], Bs + buf * 128 * GP + (warp_n * 64 + ni * 16) * GP + kk, GP);
#pragma unroll
            for (int mi = 0; mi < 2; mi++)
#pragma unroll
                for (int ni = 0; ni < 4; ni++)
                    wmma::mma_sync(c[mi][ni], af[mi], bf[ni], c[mi][ni]);
        }
    };

    // segment 0: P * P^T (K = 4096)
    {
        const __half* bA = g_Hbh + ((size_t)i0 << 12);
        const __half* bB = g_Hbh + ((size_t)j0 << 12);
        stage(0, bA, bB, NN, 0);
        const int kn = NN / GKT; // 128
        for (int t = 0; t < kn; t++) {
            asm volatile("cp.async.wait_group 0;\n" ::: "memory");
            __syncthreads();
            if (t + 1 < kn) stage((t + 1) & 1, bA, bB, NN, (t + 1) * GKT);
            compute(t & 1);
        }
        __syncthreads();
    }
    // segment 1: (pXw) * (-2 pX)^T (K = 512)
    {
        const __half* bA = g_Yb + ((size_t)i0 << 10) + 512; // pXw
        const __half* bB = g_Ya + ((size_t)j0 << 10);       // -2*pX
        stage(0, bA, bB, 1024, 0);
        const int kn = 512 / GKT; // 16
        for (int t = 0; t < kn; t++) {
            asm volatile("cp.async.wait_group 0;\n" ::: "memory");
            __syncthreads();
            if (t + 1 < kn) stage((t + 1) & 1, bA, bB, 1024, (t + 1) * GKT);
            compute(t & 1);
        }
    }

    // epilogue: two 64-row phases through smem
    for (int p = 0; p < 2; p++) {
        __syncthreads();
        if ((warp_m >> 1) == p) {
            int lm = (warp_m & 1) * 32;
#pragma unroll
            for (int mi = 0; mi < 2; mi++)
#pragma unroll
                for (int ni = 0; ni < 4; ni++)
                    wmma::store_matrix_sync(ep + (lm + mi * 16) * EPLD + warp_n * 64 + ni * 16,
                                            c[mi][ni], EPLD, wmma::mem_row_major);
        }
        __syncthreads();

        int row0 = i0 + p * 64;

        // primary: rows row0+li, cols j0+lj..+8
        {
            int lj = (tid & 15) << 3;
#pragma unroll
            for (int q = 0; q < 4; q++) {
                int li = (tid >> 4) + q * 16;
                int gi = row0 + li;
                float ai = __ldg(&g_a[gi]);
                float bi_ = __ldg(&g_b[gi]);
                float tmp[8];
#pragma unroll
                for (int jj = 0; jj < 8; jj++) {
                    int gj = j0 + lj + jj;
                    float v = ep[li * EPLD + lj + jj] + ai * __ldg(&g_b[gj]) + bi_ * __ldg(&g_a[gj]);
                    if (gi == gj) v *= 1.f / ((float)__ldg(&g_degrow[gi]) + 1.f);
                    tmp[jj] = v;
                }
                size_t off = ((size_t)gi << 12) + j0 + lj;
                *(float4*)(out + off) = *(float4*)tmp;
                *(float4*)(out + off + 4) = *(float4*)(tmp + 4);
            }
        }

        // mirror (transposed) for off-diagonal blocks
        if (bi != bj) {
            int im = (tid & 7) << 3;
#pragma unroll
            for (int q = 0; q < 4; q++) {
                int jm = (tid >> 3) + q * 32;
                int gj = j0 + jm;
                float aj = __ldg(&g_a[gj]);
                float bj_ = __ldg(&g_b[gj]);
                float tmp[8];
#pragma unroll
                for (int ii = 0; ii < 8; ii++) {
                    int gi = row0 + im + ii;
                    tmp[ii] = ep[(im + ii) * EPLD + jm] + __ldg(&g_a[gi]) * bj_ + __ldg(&g_b[gi]) * aj;
                }
                size_t off = ((size_t)gj << 12) + row0 + im;
                *(float4*)(out + off) = *(float4*)tmp;
                *(float4*)(out + off + 4) = *(float4*)(tmp + 4);
            }
        }
    }
}

extern "C" void kernel_launch(void* const* d_in, const int* in_sizes, int n_in,
                              void* d_out, int out_size) {
    const float* x = (const float*)d_in[0];
    const float* w = (const float*)d_in[1];
    const int* ei = (const int*)d_in[2];
    const int* src = ei;
    const int* dst = ei + EE;
    float* out = (float*)d_out;

    init_kernel<<<(NN + 255) / 256, 256>>>();
    count_kernel<<<(EE + 255) / 256, 256>>>(src, dst);
    scan_kernel<<<1, 1024>>>();
    fill_kernel<<<(EE + NN + 255) / 256, 256>>>(src, dst);

    sq_kernel<<<NN, 128>>>(x, w);

    // P1 = 0.5*Ahat + 0.5*I in g_Hah
    p1_init_kernel<<<dim3(NN, 2), 256>>>();
    p1_scatter_kernel<<<(EE + NN + 255) / 256, 256>>>(src, dst);

    // 9 more hops: P10 ends in g_Hbh
    dim3 gp(NN, 2);
    for (int h = 0; h < 9; h++) {
        if (h & 1) phop_kernel<1><<<gp, 256>>>();
        else       phop_kernel<0><<<gp, 256>>>();
    }

    // thin hops: [pX | pXw] ends in g_Yb
    thop_kernel<0><<<NN, 128>>>();          // h1: Y0 -> Ya
    thop_kernel<1><<<NN, 128>>>();          // h2: Ya -> Yb
    for (int h = 3; h <= 10; h++) {
        if (h & 1) thop_kernel<2><<<NN, 128>>>(); // Yb -> Ya
        else       thop_kernel<1><<<NN, 128>>>(); // Ya -> Yb
    }

    prescale_kernel<<<NN, 64>>>();          // Ya[:,0:512] = -2*pX
    matvec_kernel<<<NN / 8, 256>>>();       // a, b

    final_gemm_kernel<<<528, 256>>>(out);
    (void)in_sizes; (void)n_in; (void)out_size;
}

// round 14
// speedup vs baseline: 2.4717x; 1.1097x over previous
#include <cuda_runtime.h>
#include <cuda_fp16.h>
#include <mma.h>

using namespace nvcuda;

#define NN 4096
#define DD 512
#define EE 65536

// ---------------- static device scratch (allocation-free rule) ----------------
__device__ __half g_Hah[(size_t)NN * NN];     // P ping
__device__ __half g_Hbh[(size_t)NN * NN];     // P pong (final P lands here)
__device__ __half g_Y0[(size_t)NN * 1024];    // [X | Xw] fp16
__device__ __half g_Ya[(size_t)NN * 1024];    // thin ping / final -2*pX
__device__ __half g_Yb[(size_t)NN * 1024];    // thin pong (final [pX | pXw])
__device__ float g_a[NN];                     // P*u
__device__ float g_b[NN];                     // P*1
__device__ int   g_rowptr[NN + 1];
__device__ int   g_cur[NN];
__device__ int   g_cols[EE + NN];
__device__ float g_vals[EE + NN];
__device__ float g_dis[NN];
__device__ float g_sq[NN];
__device__ int   g_degdst[NN];
__device__ int   g_degrow[NN];

// ---------------- streams/events for fork-join overlap (created at load time,
// host-side only; no device allocation inside kernel_launch) ----------------
struct HxStreams {
    cudaStream_t side;
    cudaEvent_t eRoot, eCsr, eSq, eSide;
    HxStreams() {
        cudaStreamCreateWithFlags(&side, cudaStreamNonBlocking);
        cudaEventCreateWithFlags(&eRoot, cudaEventDisableTiming);
        cudaEventCreateWithFlags(&eCsr, cudaEventDisableTiming);
        cudaEventCreateWithFlags(&eSq, cudaEventDisableTiming);
        cudaEventCreateWithFlags(&eSide, cudaEventDisableTiming);
    }
};
static HxStreams hx;

// ---------------- graph preprocessing ----------------
__global__ void init_kernel() {
    int i = blockIdx.x * blockDim.x + threadIdx.x;
    if (i < NN) { g_degdst[i] = 1; g_degrow[i] = 0; }
}

__global__ void count_kernel(const int* __restrict__ src, const int* __restrict__ dst) {
    int i = blockIdx.x * blockDim.x + threadIdx.x;
    if (i < EE) {
        atomicAdd(&g_degdst[dst[i]], 1);
        atomicAdd(&g_degrow[src[i]], 1);
    }
}

// single block, 1024 threads, 4 elements each: exclusive scan of g_degdst -> rowptr
__global__ void scan_kernel() {
    __shared__ int part[1024];
    int t = threadIdx.x;
    int v[4];
    int s = 0;
#pragma unroll
    for (int j = 0; j < 4; j++) { v[j] = g_degdst[t * 4 + j]; s += v[j]; }
    part[t] = s;
    __syncthreads();
    for (int off = 1; off < 1024; off <<= 1) {
        int x = 0;
        if (t >= off) x = part[t - off];
        __syncthreads();
        if (t >= off) part[t] += x;
        __syncthreads();
    }
    int base = part[t] - s;
    int run = base;
#pragma unroll
    for (int j = 0; j < 4; j++) {
        int idx = t * 4 + j;
        g_rowptr[idx] = run;
        g_cur[idx] = run;
        g_dis[idx] = rsqrtf((float)v[j]);
        run += v[j];
    }
    if (t == 1023) g_rowptr[NN] = part[1023];
}

__global__ void fill_kernel(const int* __restrict__ src, const int* __restrict__ dst) {
    int i = blockIdx.x * blockDim.x + threadIdx.x;
    if (i < EE) {
        int s = src[i], d = dst[i];
        int p = atomicAdd(&g_cur[d], 1);
        g_cols[p] = s;
        g_vals[p] = g_dis[s] * g_dis[d];
    } else if (i < EE + NN) {
        int n = i - EE;
        int p = atomicAdd(&g_cur[n], 1);
        g_cols[p] = n;
        g_vals[p] = g_dis[n] * g_dis[n];
    }
}

// ---------------- sq + Y0 build (side stream; inputs only) ----------------
__global__ void sq_kernel(const float* __restrict__ x, const float* __restrict__ w) {
    __shared__ float red[4];
    int r = blockIdx.x;
    int t = threadIdx.x;
    float s = 0.f;
    for (int d = t; d < DD; d += 128) {
        float xv = x[r * DD + d];
        float wv = w[d];
        s += wv * xv * xv;
        g_Y0[(size_t)r * 1024 + d] = __float2half_rn(xv);
        g_Y0[(size_t)r * 1024 + 512 + d] = __float2half_rn(xv * wv);
    }
#pragma unroll
    for (int o = 16; o > 0; o >>= 1) s += __shfl_xor_sync(0xffffffffu, s, o);
    if ((t & 31) == 0) red[t >> 5] = s;
    __syncthreads();
    if (t == 0) g_sq[r] = red[0] + red[1] + red[2] + red[3];
}

// ---------------- P1 = 0.5*Ahat + 0.5*I ----------------
__global__ void p1_init_kernel() {
    int r = blockIdx.x;
    int c = (blockIdx.y << 11) + (threadIdx.x << 3);
    uint4 z = make_uint4(0u, 0u, 0u, 0u);
    *(uint4*)(g_Hah + (size_t)r * NN + c) = z;
    if (r >= c && r < c + 8) g_Hah[(size_t)r * NN + r] = __float2half_rn(0.5f);
}

__global__ void p1_scatter_kernel(const int* __restrict__ src, const int* __restrict__ dst) {
    int i = blockIdx.x * blockDim.x + threadIdx.x;
    if (i < EE) {
        int s = src[i], d = dst[i];
        atomicAdd(&g_Hah[(size_t)d * NN + s], __float2half_rn(0.5f * g_dis[s] * g_dis[d]));
    } else if (i < EE + NN) {
        int n = i - EE;
        atomicAdd(&g_Hah[(size_t)n * NN + n], __float2half_rn(0.5f * g_dis[n] * g_dis[n]));
    }
}

// ---------------- accumulate helper ----------------
#define ACC8(u, v)                                                              \
    {                                                                           \
        __half2* hp_ = (__half2*)&(u);                                          \
        float2 f0_ = __half22float2(hp_[0]);                                    \
        float2 f1_ = __half22float2(hp_[1]);                                    \
        float2 f2_ = __half22float2(hp_[2]);                                    \
        float2 f3_ = __half22float2(hp_[3]);                                    \
        acc[0] = fmaf((v), f0_.x, acc[0]); acc[1] = fmaf((v), f0_.y, acc[1]);   \
        acc[2] = fmaf((v), f1_.x, acc[2]); acc[3] = fmaf((v), f1_.y, acc[3]);   \
        acc[4] = fmaf((v), f2_.x, acc[4]); acc[5] = fmaf((v), f2_.y, acc[5]);   \
        acc[6] = fmaf((v), f3_.x, acc[6]); acc[7] = fmaf((v), f3_.y, acc[7]);   \
    }

// ---------------- P-build hop: O = 0.5 * Ahat * H + 0.5 * I ----------------
template <int DIR>
__global__ __launch_bounds__(256) void phop_kernel() {
    const __half* __restrict__ H = DIR ? g_Hbh : g_Hah;
    __half* __restrict__ O = DIR ? g_Hah : g_Hbh;
    int r = blockIdx.x;
    int c = (blockIdx.y << 11) + (threadIdx.x << 3);
    int beg = __ldg(&g_rowptr[r]);
    int end = __ldg(&g_rowptr[r + 1]);

    float acc[8];
#pragma unroll
    for (int i = 0; i < 8; i++) acc[i] = 0.f;

    int e = beg;
    for (; e + 4 <= end; e += 4) {
        int   i0 = __ldg(&g_cols[e + 0]);
        int   i1 = __ldg(&g_cols[e + 1]);
        int   i2 = __ldg(&g_cols[e + 2]);
        int   i3 = __ldg(&g_cols[e + 3]);
        float v0 = __ldg(&g_vals[e + 0]);
        float v1 = __ldg(&g_vals[e + 1]);
        float v2 = __ldg(&g_vals[e + 2]);
        float v3 = __ldg(&g_vals[e + 3]);
        uint4 u0 = __ldg((const uint4*)(H + ((size_t)i0 << 12) + c));
        uint4 u1 = __ldg((const uint4*)(H + ((size_t)i1 << 12) + c));
        uint4 u2 = __ldg((const uint4*)(H + ((size_t)i2 << 12) + c));
        uint4 u3 = __ldg((const uint4*)(H + ((size_t)i3 << 12) + c));
        ACC8(u0, v0);
        ACC8(u1, v1);
        ACC8(u2, v2);
        ACC8(u3, v3);
    }
    for (; e < end; e++) {
        int   i0 = __ldg(&g_cols[e]);
        float v0 = __ldg(&g_vals[e]);
        uint4 u0 = __ldg((const uint4*)(H + ((size_t)i0 << 12) + c));
        ACC8(u0, v0);
    }

    int dr = r - c;
    __half2 o[4];
#pragma unroll
    for (int q = 0; q < 4; q++) {
        float f0 = 0.5f * acc[2 * q];
        float f1 = 0.5f * acc[2 * q + 1];
        if (dr == 2 * q) f0 += 0.5f;
        if (dr == 2 * q + 1) f1 += 0.5f;
        o[q] = __floats2half2_rn(f0, f1);
    }
    *(uint4*)(O + ((size_t)r << 12) + c) = *(uint4*)o;
}

// ---------------- thin hop on Y (1024 cols) ----------------
// S == 0: Y0 -> Ya ; S == 1: Ya -> Yb ; S == 2: Yb -> Ya
template <int S>
__global__ __launch_bounds__(128) void thop_kernel() {
    const __half* __restrict__ H = (S == 0) ? g_Y0 : ((S == 1) ? g_Ya : g_Yb);
    __half* __restrict__ O = (S == 0) ? g_Ya : ((S == 1) ? g_Yb : g_Ya);
    int r = blockIdx.x;
    int c = threadIdx.x << 3;
    int beg = __ldg(&g_rowptr[r]);
    int end = __ldg(&g_rowptr[r + 1]);

    float acc[8];
#pragma unroll
    for (int i = 0; i < 8; i++) acc[i] = 0.f;

    int e = beg;
    for (; e + 4 <= end; e += 4) {
        int   i0 = __ldg(&g_cols[e + 0]);
        int   i1 = __ldg(&g_cols[e + 1]);
        int   i2 = __ldg(&g_cols[e + 2]);
        int   i3 = __ldg(&g_cols[e + 3]);
        float v0 = __ldg(&g_vals[e + 0]);
        float v1 = __ldg(&g_vals[e + 1]);
        float v2 = __ldg(&g_vals[e + 2]);
        float v3 = __ldg(&g_vals[e + 3]);
        uint4 u0 = __ldg((const uint4*)(H + ((size_t)i0 << 10) + c));
        uint4 u1 = __ldg((const uint4*)(H + ((size_t)i1 << 10) + c));
        uint4 u2 = __ldg((const uint4*)(H + ((size_t)i2 << 10) + c));
        uint4 u3 = __ldg((const uint4*)(H + ((size_t)i3 << 10) + c));
        ACC8(u0, v0);
        ACC8(u1, v1);
        ACC8(u2, v2);
        ACC8(u3, v3);
    }
    for (; e < end; e++) {
        int   i0 = __ldg(&g_cols[e]);
        float v0 = __ldg(&g_vals[e]);
        uint4 u0 = __ldg((const uint4*)(H + ((size_t)i0 << 10) + c));
        ACC8(u0, v0);
    }

    uint4 ux = __ldg((const uint4*)(g_Y0 + ((size_t)r << 10) + c));
    __half2* xp = (__half2*)&ux;
    __half2 o[4];
#pragma unroll
    for (int q = 0; q < 4; q++) {
        float2 xf = __half22float2(xp[q]);
        o[q] = __floats2half2_rn(0.5f * acc[2 * q] + 0.5f * xf.x,
                                 0.5f * acc[2 * q + 1] + 0.5f * xf.y);
    }
    *(uint4*)(O + ((size_t)r << 10) + c) = *(uint4*)o;
}

// ---------------- prescale: Ya[:, 0:512] = -2 * Yb[:, 0:512] ----------------
__global__ void prescale_kernel() {
    int r = blockIdx.x;
    int c = threadIdx.x << 3;
    uint4 u = *(const uint4*)(g_Yb + ((size_t)r << 10) + c);
    __half2* hp = (__half2*)&u;
    __half2 m2 = __floats2half2_rn(-2.f, -2.f);
#pragma unroll
    for (int q = 0; q < 4; q++) hp[q] = __hmul2(hp[q], m2);
    *(uint4*)(g_Ya + ((size_t)r << 10) + c) = u;
}

// ---------------- a = P*u, b = P*1 ----------------
__global__ __launch_bounds__(256) void matvec_kernel() {
    int lane = threadIdx.x & 31;
    int wid = threadIdx.x >> 5;
    int r = blockIdx.x * 8 + wid;
    const __half* Pr = g_Hbh + ((size_t)r << 12);
    float sa = 0.f, sb = 0.f;
    for (int t = lane; t < NN / 8; t += 32) {
        uint4 u = __ldg((const uint4*)(Pr + t * 8));
        __half2* hp = (__half2*)&u;
        float4 w0 = __ldg((const float4*)(g_sq + t * 8));
        float4 w1 = __ldg((const float4*)(g_sq + t * 8 + 4));
        float2 f0 = __half22float2(hp[0]);
        float2 f1 = __half22float2(hp[1]);
        float2 f2 = __half22float2(hp[2]);
        float2 f3 = __half22float2(hp[3]);
        sa += f0.x * w0.x + f0.y * w0.y + f1.x * w0.z + f1.y * w0.w
            + f2.x * w1.x + f2.y * w1.y + f3.x * w1.z + f3.y * w1.w;
        sb += f0.x + f0.y + f1.x + f1.y + f2.x + f2.y + f3.x + f3.y;
    }
#pragma unroll
    for (int o = 16; o > 0; o >>= 1) {
        sa += __shfl_xor_sync(0xffffffffu, sa, o);
        sb += __shfl_xor_sync(0xffffffffu, sb, o);
    }
    if (lane == 0) { g_a[r] = sa; g_b[r] = sb; }
}

// ---------------- fused final GEMM (wmma, fp16->fp32) ----------------
// out = P*P^T - 2*(pXw)(pX)^T + a*b^T + b*a^T, diag /(deg_row+1).
#define GKT 32
#define GP 40     // smem pitch (halves)
#define EPLD 136  // epilogue float pitch (mult of 4)

__global__ __launch_bounds__(256) void final_gemm_kernel(float* __restrict__ out) {
    __shared__ alignas(16) unsigned char sraw[2 * 128 * GP * 2 * 2]; // 40960 B
    __half* As = (__half*)sraw;                    // [2][128][GP]
    __half* Bs = (__half*)(sraw + 2 * 128 * GP * 2);
    float* ep = (float*)sraw;                      // epilogue reuse (34816 B)

    int tid = threadIdx.x;
    int wid = tid >> 5;
    int warp_m = wid >> 1;
    int warp_n = wid & 1;

    int bid = blockIdx.x;
    int bi = (int)((sqrtf(8.f * (float)bid + 1.f) - 1.f) * 0.5f);
    while ((bi + 1) * (bi + 2) / 2 <= bid) bi++;
    while (bi * (bi + 1) / 2 > bid) bi--;
    int bj = bid - bi * (bi + 1) / 2;
    int i0 = bi << 7;
    int j0 = bj << 7;

    wmma::fragment<wmma::accumulator, 16, 16, 16, float> c[2][4];
#pragma unroll
    for (int mi = 0; mi < 2; mi++)
#pragma unroll
        for (int ni = 0; ni < 4; ni++) wmma::fill_fragment(c[mi][ni], 0.f);

    auto stage = [&](int buf, const __half* bA, const __half* bB, int ldx, int k0) {
#pragma unroll
        for (int j = 0; j < 2; j++) {
            int idx = tid * 2 + j;
            int row = idx >> 2;
            int kq = idx & 3;
            const __half* ga = bA + (size_t)row * ldx + k0 + kq * 8;
            const __half* gb = bB + (size_t)row * ldx + k0 + kq * 8;
            unsigned int sa = (unsigned int)__cvta_generic_to_shared(As + buf * 128 * GP + row * GP + kq * 8);
            unsigned int sb = (unsigned int)__cvta_generic_to_shared(Bs + buf * 128 * GP + row * GP + kq * 8);
            asm volatile("cp.async.ca.shared.global [%0], [%1], 16;\n" ::"r"(sa), "l"(ga) : "memory");
            asm volatile("cp.async.ca.shared.global [%0], [%1], 16;\n" ::"r"(sb), "l"(gb) : "memory");
        }
        asm volatile("cp.async.commit_group;\n" ::: "memory");
    };

    auto compute = [&](int buf) {
#pragma unroll
        for (int kk = 0; kk < GKT; kk += 16) {
            wmma::fragment<wmma::matrix_a, 16, 16, 16, __half, wmma::row_major> af[2];
            wmma::fragment<wmma::matrix_b, 16, 16, 16, __half, wmma::col_major> bf[4];
#pragma unroll
            for (int mi = 0; mi < 2; mi++)
                wmma::load_matrix_sync(af[mi], As + buf * 128 * GP + (warp_m * 32 + mi * 16) * GP + kk, GP);
#pragma unroll
            for (int ni = 0; ni < 4; ni++)
                wmma::load_matrix_sync(bf[ni], Bs + buf * 128 * GP + (warp_n * 64 + ni * 16) * GP + kk, GP);
#pragma unroll
            for (int mi = 0; mi < 2; mi++)
#pragma unroll
                for (int ni = 0; ni < 4; ni++)
                    wmma::mma_sync(c[mi][ni], af[mi], bf[ni], c[mi][ni]);
        }
    };

    // segment 0: P * P^T (K = 4096)
    {
        const __half* bA = g_Hbh + ((size_t)i0 << 12);
        const __half* bB = g_Hbh + ((size_t)j0 << 12);
        stage(0, bA, bB, NN, 0);
        const int kn = NN / GKT; // 128
        for (int t = 0; t < kn; t++) {
            asm volatile("cp.async.wait_group 0;\n" ::: "memory");
            __syncthreads();
            if (t + 1 < kn) stage((t + 1) & 1, bA, bB, NN, (t + 1) * GKT);
            compute(t & 1);
        }
        __syncthreads();
    }
    // segment 1: (pXw) * (-2 pX)^T (K = 512)
    {
        const __half* bA = g_Yb + ((size_t)i0 << 10) + 512; // pXw
        const __half* bB = g_Ya + ((size_t)j0 << 10);       // -2*pX
        stage(0, bA, bB, 1024, 0);
        const int kn = 512 / GKT; // 16
        for (int t = 0; t < kn; t++) {
            asm volatile("cp.async.wait_group 0;\n" ::: "memory");
            __syncthreads();
            if (t + 1 < kn) stage((t + 1) & 1, bA, bB, 1024, (t + 1) * GKT);
            compute(t & 1);
        }
    }

    // epilogue: two 64-row phases through smem
    for (int p = 0; p < 2; p++) {
        __syncthreads();
        if ((warp_m >> 1) == p) {
            int lm = (warp_m & 1) * 32;
#pragma unroll
            for (int mi = 0; mi < 2; mi++)
#pragma unroll
                for (int ni = 0; ni < 4; ni++)
                    wmma::store_matrix_sync(ep + (lm + mi * 16) * EPLD + warp_n * 64 + ni * 16,
                                            c[mi][ni], EPLD, wmma::mem_row_major);
        }
        __syncthreads();

        int row0 = i0 + p * 64;

        // primary: rows row0+li, cols j0+lj..+8
        {
            int lj = (tid & 15) << 3;
#pragma unroll
            for (int q = 0; q < 4; q++) {
                int li = (tid >> 4) + q * 16;
                int gi = row0 + li;
                float ai = __ldg(&g_a[gi]);
                float bi_ = __ldg(&g_b[gi]);
                float tmp[8];
#pragma unroll
                for (int jj = 0; jj < 8; jj++) {
                    int gj = j0 + lj + jj;
                    float v = ep[li * EPLD + lj + jj] + ai * __ldg(&g_b[gj]) + bi_ * __ldg(&g_a[gj]);
                    if (gi == gj) v *= 1.f / ((float)__ldg(&g_degrow[gi]) + 1.f);
                    tmp[jj] = v;
                }
                size_t off = ((size_t)gi << 12) + j0 + lj;
                *(float4*)(out + off) = *(float4*)tmp;
                *(float4*)(out + off + 4) = *(float4*)(tmp + 4);
            }
        }

        // mirror (transposed) for off-diagonal blocks
        if (bi != bj) {
            int im = (tid & 7) << 3;
#pragma unroll
            for (int q = 0; q < 4; q++) {
                int jm = (tid >> 3) + q * 32;
                int gj = j0 + jm;
                float aj = __ldg(&g_a[gj]);
                float bj_ = __ldg(&g_b[gj]);
                float tmp[8];
#pragma unroll
                for (int ii = 0; ii < 8; ii++) {
                    int gi = row0 + im + ii;
                    tmp[ii] = ep[(im + ii) * EPLD + jm] + __ldg(&g_a[gi]) * bj_ + __ldg(&g_b[gi]) * aj;
                }
                size_t off = ((size_t)gj << 12) + row0 + im;
                *(float4*)(out + off) = *(float4*)tmp;
                *(float4*)(out + off + 4) = *(float4*)(tmp + 4);
            }
        }
    }
}

extern "C" void kernel_launch(void* const* d_in, const int* in_sizes, int n_in,
                              void* d_out, int out_size) {
    const float* x = (const float*)d_in[0];
    const float* w = (const float*)d_in[1];
    const int* ei = (const int*)d_in[2];
    const int* src = ei;
    const int* dst = ei + EE;
    float* out = (float*)d_out;

    // ---- fork: side stream starts sq (depends only on inputs) ----
    cudaEventRecord(hx.eRoot, 0);
    cudaStreamWaitEvent(hx.side, hx.eRoot, 0);
    sq_kernel<<<NN, 128, 0, hx.side>>>(x, w);
    cudaEventRecord(hx.eSq, hx.side);

    // ---- main: CSR build ----
    init_kernel<<<(NN + 255) / 256, 256>>>();
    count_kernel<<<(EE + 255) / 256, 256>>>(src, dst);
    scan_kernel<<<1, 1024>>>();
    fill_kernel<<<(EE + NN + 255) / 256, 256>>>(src, dst);
    cudaEventRecord(hx.eCsr, 0);

    // ---- side: thin hops (need CSR + sq) + separate prescale ----
    cudaStreamWaitEvent(hx.side, hx.eCsr, 0);
    thop_kernel<0><<<NN, 128, 0, hx.side>>>();   // Y0 -> Ya
    thop_kernel<1><<<NN, 128, 0, hx.side>>>();   // Ya -> Yb
    for (int h = 3; h <= 10; h++) {
        if (h & 1) thop_kernel<2><<<NN, 128, 0, hx.side>>>(); // Yb -> Ya
        else       thop_kernel<1><<<NN, 128, 0, hx.side>>>(); // Ya -> Yb
    }
    // result [pX | pXw] in g_Yb; prescale reads Yb, writes Ya (no race)
    prescale_kernel<<<NN, 64, 0, hx.side>>>();
    cudaEventRecord(hx.eSide, hx.side);

    // ---- main: P chain (wait for sq: matvec reads g_sq) ----
    cudaStreamWaitEvent(0, hx.eSq, 0);
    p1_init_kernel<<<dim3(NN, 2), 256>>>();
    p1_scatter_kernel<<<(EE + NN + 255) / 256, 256>>>(src, dst);
    dim3 gp(NN, 2);
    for (int h = 0; h < 9; h++) {
        if (h & 1) phop_kernel<1><<<gp, 256>>>();
        else       phop_kernel<0><<<gp, 256>>>();
    }
    matvec_kernel<<<NN / 8, 256>>>();   // needs g_Hbh (P) + g_sq

    // ---- join, then final GEMM ----
    cudaStreamWaitEvent(0, hx.eSide, 0);
    final_gemm_kernel<<<528, 256>>>(out);
    (void)in_sizes; (void)n_in; (void)out_size;
}

// round 15
// speedup vs baseline: 2.4817x; 1.0040x over previous
#include <cuda_runtime.h>
#include <cuda_fp16.h>
#include <mma.h>

using namespace nvcuda;

#define NN 4096
#define DD 512
#define EE 65536

// ---------------- static device scratch (allocation-free rule) ----------------
__device__ __half g_Hah[(size_t)NN * NN];     // P ping
__device__ __half g_Hbh[(size_t)NN * NN];     // P pong (final P lands here)
__device__ __half g_Y0[(size_t)NN * 1024];    // [X | Xw] fp16
__device__ __half g_Ya[(size_t)NN * 1024];    // thin ping / final -2*pX
__device__ __half g_Yb[(size_t)NN * 1024];    // thin pong (final [pX | pXw])
__device__ float g_a[NN];                     // P*u
__device__ float g_b[NN];                     // P*1
__device__ int   g_rowptr[NN + 1];
__device__ int   g_cur[NN];
__device__ int   g_cols[EE + NN];
__device__ float g_vals[EE + NN];
__device__ float g_dis[NN];
__device__ float g_sq[NN];
__device__ int   g_degdst[NN];
__device__ int   g_degrow[NN];

// ---------------- streams/events for fork-join overlap (created at load time,
// host-side only; no device allocation inside kernel_launch) ----------------
struct HxStreams {
    cudaStream_t side;
    cudaEvent_t eRoot, eCsr, eSq, eSide;
    HxStreams() {
        cudaStreamCreateWithFlags(&side, cudaStreamNonBlocking);
        cudaEventCreateWithFlags(&eRoot, cudaEventDisableTiming);
        cudaEventCreateWithFlags(&eCsr, cudaEventDisableTiming);
        cudaEventCreateWithFlags(&eSq, cudaEventDisableTiming);
        cudaEventCreateWithFlags(&eSide, cudaEventDisableTiming);
    }
};
static HxStreams hx;

// ---------------- graph preprocessing ----------------
__global__ void init_kernel() {
    int i = blockIdx.x * blockDim.x + threadIdx.x;
    if (i < NN) { g_degdst[i] = 1; g_degrow[i] = 0; }
}

__global__ void count_kernel(const int* __restrict__ src, const int* __restrict__ dst) {
    int i = blockIdx.x * blockDim.x + threadIdx.x;
    if (i < EE) {
        atomicAdd(&g_degdst[dst[i]], 1);
        atomicAdd(&g_degrow[src[i]], 1);
    }
}

// single block, 1024 threads, 4 elements each: exclusive scan of g_degdst -> rowptr
__global__ void scan_kernel() {
    __shared__ int part[1024];
    int t = threadIdx.x;
    int v[4];
    int s = 0;
#pragma unroll
    for (int j = 0; j < 4; j++) { v[j] = g_degdst[t * 4 + j]; s += v[j]; }
    part[t] = s;
    __syncthreads();
    for (int off = 1; off < 1024; off <<= 1) {
        int x = 0;
        if (t >= off) x = part[t - off];
        __syncthreads();
        if (t >= off) part[t] += x;
        __syncthreads();
    }
    int base = part[t] - s;
    int run = base;
#pragma unroll
    for (int j = 0; j < 4; j++) {
        int idx = t * 4 + j;
        g_rowptr[idx] = run;
        g_cur[idx] = run;
        g_dis[idx] = rsqrtf((float)v[j]);
        run += v[j];
    }
    if (t == 1023) g_rowptr[NN] = part[1023];
}

__global__ void fill_kernel(const int* __restrict__ src, const int* __restrict__ dst) {
    int i = blockIdx.x * blockDim.x + threadIdx.x;
    if (i < EE) {
        int s = src[i], d = dst[i];
        int p = atomicAdd(&g_cur[d], 1);
        g_cols[p] = s;
        g_vals[p] = g_dis[s] * g_dis[d];
    } else if (i < EE + NN) {
        int n = i - EE;
        int p = atomicAdd(&g_cur[n], 1);
        g_cols[p] = n;
        g_vals[p] = g_dis[n] * g_dis[n];
    }
}

// ---------------- sq + Y0 build (side stream; inputs only) ----------------
__global__ void sq_kernel(const float* __restrict__ x, const float* __restrict__ w) {
    __shared__ float red[4];
    int r = blockIdx.x;
    int t = threadIdx.x;
    float s = 0.f;
    for (int d = t; d < DD; d += 128) {
        float xv = x[r * DD + d];
        float wv = w[d];
        s += wv * xv * xv;
        g_Y0[(size_t)r * 1024 + d] = __float2half_rn(xv);
        g_Y0[(size_t)r * 1024 + 512 + d] = __float2half_rn(xv * wv);
    }
#pragma unroll
    for (int o = 16; o > 0; o >>= 1) s += __shfl_xor_sync(0xffffffffu, s, o);
    if ((t & 31) == 0) red[t >> 5] = s;
    __syncthreads();
    if (t == 0) g_sq[r] = red[0] + red[1] + red[2] + red[3];
}

// ---------------- P1 = 0.5*Ahat + 0.5*I ----------------
__global__ void p1_init_kernel() {
    int r = blockIdx.x;
    int c = (blockIdx.y << 11) + (threadIdx.x << 3);
    uint4 z = make_uint4(0u, 0u, 0u, 0u);
    *(uint4*)(g_Hah + (size_t)r * NN + c) = z;
    if (r >= c && r < c + 8) g_Hah[(size_t)r * NN + r] = __float2half_rn(0.5f);
}

__global__ void p1_scatter_kernel(const int* __restrict__ src, const int* __restrict__ dst) {
    int i = blockIdx.x * blockDim.x + threadIdx.x;
    if (i < EE) {
        int s = src[i], d = dst[i];
        atomicAdd(&g_Hah[(size_t)d * NN + s], __float2half_rn(0.5f * g_dis[s] * g_dis[d]));
    } else if (i < EE + NN) {
        int n = i - EE;
        atomicAdd(&g_Hah[(size_t)n * NN + n], __float2half_rn(0.5f * g_dis[n] * g_dis[n]));
    }
}

// ---------------- accumulate helper ----------------
#define ACC8(u, v)                                                              \
    {                                                                           \
        __half2* hp_ = (__half2*)&(u);                                          \
        float2 f0_ = __half22float2(hp_[0]);                                    \
        float2 f1_ = __half22float2(hp_[1]);                                    \
        float2 f2_ = __half22float2(hp_[2]);                                    \
        float2 f3_ = __half22float2(hp_[3]);                                    \
        acc[0] = fmaf((v), f0_.x, acc[0]); acc[1] = fmaf((v), f0_.y, acc[1]);   \
        acc[2] = fmaf((v), f1_.x, acc[2]); acc[3] = fmaf((v), f1_.y, acc[3]);   \
        acc[4] = fmaf((v), f2_.x, acc[4]); acc[5] = fmaf((v), f2_.y, acc[5]);   \
        acc[6] = fmaf((v), f3_.x, acc[6]); acc[7] = fmaf((v), f3_.y, acc[7]);   \
    }

// ---------------- P-build hop: O = 0.5 * Ahat * H + 0.5 * I ----------------
template <int DIR>
__global__ __launch_bounds__(256) void phop_kernel() {
    const __half* __restrict__ H = DIR ? g_Hbh : g_Hah;
    __half* __restrict__ O = DIR ? g_Hah : g_Hbh;
    int r = blockIdx.x;
    int c = (blockIdx.y << 11) + (threadIdx.x << 3);
    int beg = __ldg(&g_rowptr[r]);
    int end = __ldg(&g_rowptr[r + 1]);

    float acc[8];
#pragma unroll
    for (int i = 0; i < 8; i++) acc[i] = 0.f;

    int e = beg;
    for (; e + 4 <= end; e += 4) {
        int   i0 = __ldg(&g_cols[e + 0]);
        int   i1 = __ldg(&g_cols[e + 1]);
        int   i2 = __ldg(&g_cols[e + 2]);
        int   i3 = __ldg(&g_cols[e + 3]);
        float v0 = __ldg(&g_vals[e + 0]);
        float v1 = __ldg(&g_vals[e + 1]);
        float v2 = __ldg(&g_vals[e + 2]);
        float v3 = __ldg(&g_vals[e + 3]);
        uint4 u0 = __ldg((const uint4*)(H + ((size_t)i0 << 12) + c));
        uint4 u1 = __ldg((const uint4*)(H + ((size_t)i1 << 12) + c));
        uint4 u2 = __ldg((const uint4*)(H + ((size_t)i2 << 12) + c));
        uint4 u3 = __ldg((const uint4*)(H + ((size_t)i3 << 12) + c));
        ACC8(u0, v0);
        ACC8(u1, v1);
        ACC8(u2, v2);
        ACC8(u3, v3);
    }
    for (; e < end; e++) {
        int   i0 = __ldg(&g_cols[e]);
        float v0 = __ldg(&g_vals[e]);
        uint4 u0 = __ldg((const uint4*)(H + ((size_t)i0 << 12) + c));
        ACC8(u0, v0);
    }

    int dr = r - c;
    __half2 o[4];
#pragma unroll
    for (int q = 0; q < 4; q++) {
        float f0 = 0.5f * acc[2 * q];
        float f1 = 0.5f * acc[2 * q + 1];
        if (dr == 2 * q) f0 += 0.5f;
        if (dr == 2 * q + 1) f1 += 0.5f;
        o[q] = __floats2half2_rn(f0, f1);
    }
    *(uint4*)(O + ((size_t)r << 12) + c) = *(uint4*)o;
}

// ---------------- thin hop on Y (1024 cols) ----------------
// S == 0: Y0 -> Ya ; S == 1: Ya -> Yb ; S == 2: Yb -> Ya
template <int S>
__global__ __launch_bounds__(128) void thop_kernel() {
    const __half* __restrict__ H = (S == 0) ? g_Y0 : ((S == 1) ? g_Ya : g_Yb);
    __half* __restrict__ O = (S == 0) ? g_Ya : ((S == 1) ? g_Yb : g_Ya);
    int r = blockIdx.x;
    int c = threadIdx.x << 3;
    int beg = __ldg(&g_rowptr[r]);
    int end = __ldg(&g_rowptr[r + 1]);

    float acc[8];
#pragma unroll
    for (int i = 0; i < 8; i++) acc[i] = 0.f;

    int e = beg;
    for (; e + 4 <= end; e += 4) {
        int   i0 = __ldg(&g_cols[e + 0]);
        int   i1 = __ldg(&g_cols[e + 1]);
        int   i2 = __ldg(&g_cols[e + 2]);
        int   i3 = __ldg(&g_cols[e + 3]);
        float v0 = __ldg(&g_vals[e + 0]);
        float v1 = __ldg(&g_vals[e + 1]);
        float v2 = __ldg(&g_vals[e + 2]);
        float v3 = __ldg(&g_vals[e + 3]);
        uint4 u0 = __ldg((const uint4*)(H + ((size_t)i0 << 10) + c));
        uint4 u1 = __ldg((const uint4*)(H + ((size_t)i1 << 10) + c));
        uint4 u2 = __ldg((const uint4*)(H + ((size_t)i2 << 10) + c));
        uint4 u3 = __ldg((const uint4*)(H + ((size_t)i3 << 10) + c));
        ACC8(u0, v0);
        ACC8(u1, v1);
        ACC8(u2, v2);
        ACC8(u3, v3);
    }
    for (; e < end; e++) {
        int   i0 = __ldg(&g_cols[e]);
        float v0 = __ldg(&g_vals[e]);
        uint4 u0 = __ldg((const uint4*)(H + ((size_t)i0 << 10) + c));
        ACC8(u0, v0);
    }

    uint4 ux = __ldg((const uint4*)(g_Y0 + ((size_t)r << 10) + c));
    __half2* xp = (__half2*)&ux;
    __half2 o[4];
#pragma unroll
    for (int q = 0; q < 4; q++) {
        float2 xf = __half22float2(xp[q]);
        o[q] = __floats2half2_rn(0.5f * acc[2 * q] + 0.5f * xf.x,
                                 0.5f * acc[2 * q + 1] + 0.5f * xf.y);
    }
    *(uint4*)(O + ((size_t)r << 10) + c) = *(uint4*)o;
}

// ---------------- prescale: Ya[:, 0:512] = -2 * Yb[:, 0:512] ----------------
__global__ void prescale_kernel() {
    int r = blockIdx.x;
    int c = threadIdx.x << 3;
    uint4 u = *(const uint4*)(g_Yb + ((size_t)r << 10) + c);
    __half2* hp = (__half2*)&u;
    __half2 m2 = __floats2half2_rn(-2.f, -2.f);
#pragma unroll
    for (int q = 0; q < 4; q++) hp[q] = __hmul2(hp[q], m2);
    *(uint4*)(g_Ya + ((size_t)r << 10) + c) = u;
}

// ---------------- a = P*u, b = P*1 ----------------
__global__ __launch_bounds__(256) void matvec_kernel() {
    int lane = threadIdx.x & 31;
    int wid = threadIdx.x >> 5;
    int r = blockIdx.x * 8 + wid;
    const __half* Pr = g_Hbh + ((size_t)r << 12);
    float sa = 0.f, sb = 0.f;
    for (int t = lane; t < NN / 8; t += 32) {
        uint4 u = __ldg((const uint4*)(Pr + t * 8));
        __half2* hp = (__half2*)&u;
        float4 w0 = __ldg((const float4*)(g_sq + t * 8));
        float4 w1 = __ldg((const float4*)(g_sq + t * 8 + 4));
        float2 f0 = __half22float2(hp[0]);
        float2 f1 = __half22float2(hp[1]);
        float2 f2 = __half22float2(hp[2]);
        float2 f3 = __half22float2(hp[3]);
        sa += f0.x * w0.x + f0.y * w0.y + f1.x * w0.z + f1.y * w0.w
            + f2.x * w1.x + f2.y * w1.y + f3.x * w1.z + f3.y * w1.w;
        sb += f0.x + f0.y + f1.x + f1.y + f2.x + f2.y + f3.x + f3.y;
    }
#pragma unroll
    for (int o = 16; o > 0; o >>= 1) {
        sa += __shfl_xor_sync(0xffffffffu, sa, o);
        sb += __shfl_xor_sync(0xffffffffu, sb, o);
    }
    if (lane == 0) { g_a[r] = sa; g_b[r] = sb; }
}

// ---------------- fused final GEMM (wmma, fp16->fp32) ----------------
// out = P*P^T - 2*(pXw)(pX)^T + a*b^T + b*a^T, diag /(deg_row+1).
// __launch_bounds__(256, 2): 2 CTAs/SM -> 4 warps/SMSP to hide LDS/cp.async latency.
#define GKT 32
#define GP 40     // smem pitch (halves)
#define EPLD 136  // epilogue float pitch (mult of 4)

__global__ __launch_bounds__(256, 2) void final_gemm_kernel(float* __restrict__ out) {
    __shared__ alignas(16) unsigned char sraw[2 * 128 * GP * 2 * 2]; // 40960 B
    __half* As = (__half*)sraw;                    // [2][128][GP]
    __half* Bs = (__half*)(sraw + 2 * 128 * GP * 2);
    float* ep = (float*)sraw;                      // epilogue reuse (34816 B)

    int tid = threadIdx.x;
    int wid = tid >> 5;
    int warp_m = wid >> 1;
    int warp_n = wid & 1;

    int bid = blockIdx.x;
    int bi = (int)((sqrtf(8.f * (float)bid + 1.f) - 1.f) * 0.5f);
    while ((bi + 1) * (bi + 2) / 2 <= bid) bi++;
    while (bi * (bi + 1) / 2 > bid) bi--;
    int bj = bid - bi * (bi + 1) / 2;
    int i0 = bi << 7;
    int j0 = bj << 7;

    wmma::fragment<wmma::accumulator, 16, 16, 16, float> c[2][4];
#pragma unroll
    for (int mi = 0; mi < 2; mi++)
#pragma unroll
        for (int ni = 0; ni < 4; ni++) wmma::fill_fragment(c[mi][ni], 0.f);

    auto stage = [&](int buf, const __half* bA, const __half* bB, int ldx, int k0) {
#pragma unroll
        for (int j = 0; j < 2; j++) {
            int idx = tid * 2 + j;
            int row = idx >> 2;
            int kq = idx & 3;
            const __half* ga = bA + (size_t)row * ldx + k0 + kq * 8;
            const __half* gb = bB + (size_t)row * ldx + k0 + kq * 8;
            unsigned int sa = (unsigned int)__cvta_generic_to_shared(As + buf * 128 * GP + row * GP + kq * 8);
            unsigned int sb = (unsigned int)__cvta_generic_to_shared(Bs + buf * 128 * GP + row * GP + kq * 8);
            asm volatile("cp.async.ca.shared.global [%0], [%1], 16;\n" ::"r"(sa), "l"(ga) : "memory");
            asm volatile("cp.async.ca.shared.global [%0], [%1], 16;\n" ::"r"(sb), "l"(gb) : "memory");
        }
        asm volatile("cp.async.commit_group;\n" ::: "memory");
    };

    auto compute = [&](int buf) {
#pragma unroll
        for (int kk = 0; kk < GKT; kk += 16) {
            wmma::fragment<wmma::matrix_a, 16, 16, 16, __half, wmma::row_major> af[2];
            wmma::fragment<wmma::matrix_b, 16, 16, 16, __half, wmma::col_major> bf[4];
#pragma unroll
            for (int mi = 0; mi < 2; mi++)
                wmma::load_matrix_sync(af[mi], As + buf * 128 * GP + (warp_m * 32 + mi * 16) * GP + kk, GP);
#pragma unroll
            for (int ni = 0; ni < 4; ni++)
                wmma::load_matrix_sync(bf[ni], Bs + buf * 128 * GP + (warp_n * 64 + ni * 16) * GP + kk, GP);
#pragma unroll
            for (int mi = 0; mi < 2; mi++)
#pragma unroll
                for (int ni = 0; ni < 4; ni++)
                    wmma::mma_sync(c[mi][ni], af[mi], bf[ni], c[mi][ni]);
        }
    };

    // segment 0: P * P^T (K = 4096)
    {
        const __half* bA = g_Hbh + ((size_t)i0 << 12);
        const __half* bB = g_Hbh + ((size_t)j0 << 12);
        stage(0, bA, bB, NN, 0);
        const int kn = NN / GKT; // 128
        for (int t = 0; t < kn; t++) {
            asm volatile("cp.async.wait_group 0;\n" ::: "memory");
            __syncthreads();
            if (t + 1 < kn) stage((t + 1) & 1, bA, bB, NN, (t + 1) * GKT);
            compute(t & 1);
        }
        __syncthreads();
    }
    // segment 1: (pXw) * (-2 pX)^T (K = 512)
    {
        const __half* bA = g_Yb + ((size_t)i0 << 10) + 512; // pXw
        const __half* bB = g_Ya + ((size_t)j0 << 10);       // -2*pX
        stage(0, bA, bB, 1024, 0);
        const int kn = 512 / GKT; // 16
        for (int t = 0; t < kn; t++) {
            asm volatile("cp.async.wait_group 0;\n" ::: "memory");
            __syncthreads();
            if (t + 1 < kn) stage((t + 1) & 1, bA, bB, 1024, (t + 1) * GKT);
            compute(t & 1);
        }
    }

    // epilogue: two 64-row phases through smem
    for (int p = 0; p < 2; p++) {
        __syncthreads();
        if ((warp_m >> 1) == p) {
            int lm = (warp_m & 1) * 32;
#pragma unroll
            for (int mi = 0; mi < 2; mi++)
#pragma unroll
                for (int ni = 0; ni < 4; ni++)
                    wmma::store_matrix_sync(ep + (lm + mi * 16) * EPLD + warp_n * 64 + ni * 16,
                                            c[mi][ni], EPLD, wmma::mem_row_major);
        }
        __syncthreads();

        int row0 = i0 + p * 64;

        // primary: rows row0+li, cols j0+lj..+8
        {
            int lj = (tid & 15) << 3;
#pragma unroll
            for (int q = 0; q < 4; q++) {
                int li = (tid >> 4) + q * 16;
                int gi = row0 + li;
                float ai = __ldg(&g_a[gi]);
                float bi_ = __ldg(&g_b[gi]);
                float tmp[8];
#pragma unroll
                for (int jj = 0; jj < 8; jj++) {
                    int gj = j0 + lj + jj;
                    float v = ep[li * EPLD + lj + jj] + ai * __ldg(&g_b[gj]) + bi_ * __ldg(&g_a[gj]);
                    if (gi == gj) v *= 1.f / ((float)__ldg(&g_degrow[gi]) + 1.f);
                    tmp[jj] = v;
                }
                size_t off = ((size_t)gi << 12) + j0 + lj;
                *(float4*)(out + off) = *(float4*)tmp;
                *(float4*)(out + off + 4) = *(float4*)(tmp + 4);
            }
        }

        // mirror (transposed) for off-diagonal blocks
        if (bi != bj) {
            int im = (tid & 7) << 3;
#pragma unroll
            for (int q = 0; q < 4; q++) {
                int jm = (tid >> 3) + q * 32;
                int gj = j0 + jm;
                float aj = __ldg(&g_a[gj]);
                float bj_ = __ldg(&g_b[gj]);
                float tmp[8];
#pragma unroll
                for (int ii = 0; ii < 8; ii++) {
                    int gi = row0 + im + ii;
                    tmp[ii] = ep[(im + ii) * EPLD + jm] + __ldg(&g_a[gi]) * bj_ + __ldg(&g_b[gi]) * aj;
                }
                size_t off = ((size_t)gj << 12) + row0 + im;
                *(float4*)(out + off) = *(float4*)tmp;
                *(float4*)(out + off + 4) = *(float4*)(tmp + 4);
            }
        }
    }
}

extern "C" void kernel_launch(void* const* d_in, const int* in_sizes, int n_in,
                              void* d_out, int out_size) {
    const float* x = (const float*)d_in[0];
    const float* w = (const float*)d_in[1];
    const int* ei = (const int*)d_in[2];
    const int* src = ei;
    const int* dst = ei + EE;
    float* out = (float*)d_out;

    // ---- fork: side stream starts sq (depends only on inputs) ----
    cudaEventRecord(hx.eRoot, 0);
    cudaStreamWaitEvent(hx.side, hx.eRoot, 0);
    sq_kernel<<<NN, 128, 0, hx.side>>>(x, w);
    cudaEventRecord(hx.eSq, hx.side);

    // ---- main: CSR build ----
    init_kernel<<<(NN + 255) / 256, 256>>>();
    count_kernel<<<(EE + 255) / 256, 256>>>(src, dst);
    scan_kernel<<<1, 1024>>>();
    fill_kernel<<<(EE + NN + 255) / 256, 256>>>(src, dst);
    cudaEventRecord(hx.eCsr, 0);

    // ---- side: thin hops (need CSR + sq) + separate prescale ----
    cudaStreamWaitEvent(hx.side, hx.eCsr, 0);
    thop_kernel<0><<<NN, 128, 0, hx.side>>>();   // Y0 -> Ya
    thop_kernel<1><<<NN, 128, 0, hx.side>>>();   // Ya -> Yb
    for (int h = 3; h <= 10; h++) {
        if (h & 1) thop_kernel<2><<<NN, 128, 0, hx.side>>>(); // Yb -> Ya
        else       thop_kernel<1><<<NN, 128, 0, hx.side>>>(); // Ya -> Yb
    }
    // result [pX | pXw] in g_Yb; prescale reads Yb, writes Ya (no race)
    prescale_kernel<<<NN, 64, 0, hx.side>>>();
    cudaEventRecord(hx.eSide, hx.side);

    // ---- main: P chain (wait for sq: matvec reads g_sq) ----
    cudaStreamWaitEvent(0, hx.eSq, 0);
    p1_init_kernel<<<dim3(NN, 2), 256>>>();
    p1_scatter_kernel<<<(EE + NN + 255) / 256, 256>>>(src, dst);
    dim3 gp(NN, 2);
    for (int h = 0; h < 9; h++) {
        if (h & 1) phop_kernel<1><<<gp, 256>>>();
        else       phop_kernel<0><<<gp, 256>>>();
    }
    matvec_kernel<<<NN / 8, 256>>>();   // needs g_Hbh (P) + g_sq

    // ---- join, then final GEMM ----
    cudaStreamWaitEvent(0, hx.eSide, 0);
    final_gemm_kernel<<<528, 256>>>(out);
    (void)in_sizes; (void)n_in; (void)out_size;
}